// round 14
// baseline (speedup 1.0000x reference)
#include <cuda_runtime.h>
#include <cuda_bf16.h>
#include <cuda_fp16.h>
#include <cstdint>
#include <math.h>

#define D_MODEL   1024
#define NUM_HEADS 16
#define DEPTH     64
#define BB        2
#define SS        2048
#define MROWS     (BB * SS)                              // 4096
#define ATTN_ELEMS ((size_t)BB * NUM_HEADS * SS * SS)    // 134,217,728
#define OUT_ELEMS  ((size_t)MROWS * D_MODEL)             // 4,194,304
#define NZ        (BB * NUM_HEADS)                       // 32
#define RS_W      128
#define NELEM     (MROWS * D_MODEL)                      // 4,194,304
#define WELEM     (D_MODEL * D_MODEL)                    // 1,048,576

// ---------------- scratch (static device globals; no allocations) ------------
__device__ float g_rowsum[(size_t)NZ * SS * RS_W];
__device__ __half g_e[ATTN_ELEMS];                       // unnormalized exp
__device__ __half g_in[3 * (size_t)NELEM];               // QKV inputs fp16
__device__ __half g_w[4 * (size_t)WELEM];                // Wq,Wk,Wv,Wo [n][k] fp16
__device__ __half g_q_f[(size_t)NZ * SS * DEPTH];        // [z,s,d] fp16
__device__ __half g_k_f[(size_t)NZ * SS * DEPTH];        // [z,s,d] fp16
__device__ __half g_vt[(size_t)NZ * SS * DEPTH];         // [z,d,s] fp16 single
__device__ __half g_o_hi[(size_t)NELEM];                 // O fp16 hi/lo
__device__ __half g_o_lo[(size_t)NELEM];
__device__ float g_attn_fallback[ATTN_ELEMS];

// ============================ PTX helpers ====================================
#define MMAH(d, a, b)                                                         \
    asm volatile("mma.sync.aligned.m16n8k16.row.col.f32.f16.f16.f32 "         \
        "{%0,%1,%2,%3}, {%4,%5,%6,%7}, {%8,%9}, {%0,%1,%2,%3};"               \
        : "+f"((d)[0]), "+f"((d)[1]), "+f"((d)[2]), "+f"((d)[3])              \
        : "r"((a)[0]), "r"((a)[1]), "r"((a)[2]), "r"((a)[3]),                 \
          "r"((b)[0]), "r"((b)[1]))

#define LDSM4(R0, R1, R2, R3, ADDR)                                           \
    asm volatile("ldmatrix.sync.aligned.m8n8.x4.shared.b16 {%0,%1,%2,%3}, [%4];" \
        : "=r"(R0), "=r"(R1), "=r"(R2), "=r"(R3) : "r"(ADDR))

#define CP16(SADDR, GPTR)                                                     \
    asm volatile("cp.async.cg.shared.global [%0], [%1], 16;"                  \
        :: "r"(SADDR), "l"(GPTR))
#define CP_COMMIT() asm volatile("cp.async.commit_group;" ::: "memory")
#define CP_WAIT1()  asm volatile("cp.async.wait_group 1;" ::: "memory")
#define CP_WAIT0()  asm volatile("cp.async.wait_group 0;" ::: "memory")

__device__ __forceinline__ uint32_t smem_u32(const void* p) {
    uint32_t a;
    asm("{ .reg .u64 t; cvta.to.shared.u64 t, %1; cvt.u32.u64 %0, t; }" : "=r"(a) : "l"(p));
    return a;
}

// ============================ split kernels ==================================
__global__ __launch_bounds__(256)
void split_in3_kernel(const float* __restrict__ Q, const float* __restrict__ K,
                      const float* __restrict__ V, __half* __restrict__ dst)
{
    int z = blockIdx.y;
    const float* A = (z == 0) ? Q : (z == 1) ? K : V;
    size_t i = (size_t)blockIdx.x * 256 + threadIdx.x;
    dst[(size_t)z * NELEM + i] = __float2half(A[i]);
}

__global__ __launch_bounds__(256)
void split_w4_kernel(const float* __restrict__ W0, const float* __restrict__ W1,
                     const float* __restrict__ W2, const float* __restrict__ W3,
                     __half* __restrict__ wt)
{
    __shared__ float t[32][33];
    int z = blockIdx.z;
    const float* W = (z == 0) ? W0 : (z == 1) ? W1 : (z == 2) ? W2 : W3;
    int tx = threadIdx.x, ty = threadIdx.y;
    int n0 = blockIdx.x * 32, k0 = blockIdx.y * 32;
#pragma unroll
    for (int j = 0; j < 4; j++)
        t[ty + j * 8][tx] = W[(size_t)(k0 + ty + j * 8) * D_MODEL + n0 + tx];
    __syncthreads();
#pragma unroll
    for (int j = 0; j < 4; j++) {
        size_t o = (size_t)z * WELEM + (size_t)(n0 + ty + j * 8) * D_MODEL + k0 + tx;
        wt[o] = __float2half(t[tx][ty + j * 8]);
    }
}

// ==================== QKV projection: fp16 x fp16, K-chunk 64 ================
#define P2PAD 72
#define P2STAGE 36864     // 2 arrays * 128*72*2
#define P2_OFF_A 0
#define P2_OFF_B 18432

__global__ __launch_bounds__(256, 2)
void proj_qkv_kernel(const __half* __restrict__ in, const __half* __restrict__ w,
                     const float* __restrict__ bq, const float* __restrict__ bk,
                     const float* __restrict__ bv,
                     __half* __restrict__ qf, __half* __restrict__ kf,
                     __half* __restrict__ vt)
{
    extern __shared__ char smem[];
    const uint32_t sb0 = smem_u32(smem);

    const int zz = blockIdx.z;
    const __half* a  = in + (size_t)zz * NELEM;
    const __half* wh = w + (size_t)zz * WELEM;
    const float* bias = (zz == 0) ? bq : (zz == 1) ? bk : bv;

    const int tid  = threadIdx.x;
    const int lane = tid & 31;
    const int wid  = tid >> 5;
    const int warpM = (wid >> 2) * 64;
    const int warpN = (wid & 3) * 32;
    const int blockRow = blockIdx.y * 128;
    const int blockCol = blockIdx.x * 128;

    const int lmRow = lane & 15;
    const int lmK   = (lane >> 4) * 8;

    float acc[4][4][4];
#pragma unroll
    for (int mt = 0; mt < 4; mt++)
#pragma unroll
        for (int nt = 0; nt < 4; nt++)
#pragma unroll
            for (int r = 0; r < 4; r++) acc[mt][nt][r] = 0.0f;

    auto load_stage = [&](int stage, int chunk) {
        const int k0 = chunk * 64;
        const uint32_t sb = sb0 + stage * P2STAGE;
#pragma unroll
        for (int j = 0; j < 4; j++) {
            int id = tid + j * 256;
            int row = id >> 3, q = id & 7;
            uint32_t so = (uint32_t)(row * 144 + q * 16);
            CP16(sb + P2_OFF_A + so, &a[(size_t)(blockRow + row) * D_MODEL + k0 + q * 8]);
            CP16(sb + P2_OFF_B + so, &wh[(size_t)(blockCol + row) * D_MODEL + k0 + q * 8]);
        }
        CP_COMMIT();
    };

    load_stage(0, 0);

    for (int chunk = 0; chunk < 16; chunk++) {
        if (chunk < 15) { load_stage((chunk + 1) & 1, chunk + 1); CP_WAIT1(); }
        else           { CP_WAIT0(); }
        __syncthreads();

        const uint32_t sb = sb0 + (chunk & 1) * P2STAGE;
        const uint32_t aBase = sb + P2_OFF_A + (uint32_t)(((warpM + lmRow) * P2PAD + lmK) * 2);
        const uint32_t bBase = sb + P2_OFF_B + (uint32_t)(((warpN + lmRow) * P2PAD + lmK) * 2);

#pragma unroll
        for (int ks = 0; ks < 4; ks++) {
            const uint32_t kOff = (uint32_t)(ks * 16 * 2);
            uint32_t aF[4][4], bH[4][2];
#pragma unroll
            for (int mt = 0; mt < 4; mt++) {
                uint32_t ad = aBase + kOff + (uint32_t)(mt * 16 * P2PAD * 2);
                LDSM4(aF[mt][0], aF[mt][1], aF[mt][2], aF[mt][3], ad);
            }
#pragma unroll
            for (int ntp = 0; ntp < 2; ntp++) {
                uint32_t bd = bBase + kOff + (uint32_t)(ntp * 16 * P2PAD * 2);
                uint32_t r0, r1, r2, r3;
                LDSM4(r0, r1, r2, r3, bd);
                bH[2 * ntp][0] = r0; bH[2 * ntp + 1][0] = r1;
                bH[2 * ntp][1] = r2; bH[2 * ntp + 1][1] = r3;
            }
#pragma unroll
            for (int mt = 0; mt < 4; mt++)
#pragma unroll
                for (int nt = 0; nt < 4; nt++)
                    MMAH(acc[mt][nt], aF[mt], bH[nt]);
        }
        __syncthreads();
    }

#pragma unroll
    for (int mt = 0; mt < 4; mt++) {
#pragma unroll
        for (int nt = 0; nt < 4; nt++) {
            int row0 = blockRow + warpM + mt * 16 + (lane >> 2);
            int col  = blockCol + warpN + nt * 8 + (lane & 3) * 2;
            float b0 = bias[col], b1 = bias[col + 1];
#pragma unroll
            for (int half = 0; half < 2; half++) {
                int r = row0 + half * 8;
                float vx = acc[mt][nt][half * 2 + 0] + b0;
                float vy = acc[mt][nt][half * 2 + 1] + b1;
                int z = (r >> 11) * NUM_HEADS + (col >> 6);
                int s = r & (SS - 1);
                int d = col & (DEPTH - 1);
                if (zz == 0) {
                    size_t o = ((size_t)z * SS + s) * DEPTH + d;
                    __half2 hp = {__float2half(vx), __float2half(vy)};
                    *(__half2*)&qf[o] = hp;
                } else if (zz == 1) {
                    size_t o = ((size_t)z * SS + s) * DEPTH + d;
                    __half2 hp = {__float2half(vx), __float2half(vy)};
                    *(__half2*)&kf[o] = hp;
                } else {
                    size_t o = ((size_t)z * DEPTH + d) * SS + s;
                    vt[o]      = __float2half(vx);
                    vt[o + SS] = __float2half(vy);
                }
            }
        }
    }
}

// ==================== output projection: O(hi/lo) x W fp16, 2 MMA ============
#define SPAD 40
#define PSTAGE 30720
#define OFF_AH 0
#define OFF_AL 10240
#define OFF_BH 20480

__global__ __launch_bounds__(256, 2)
void proj_out_kernel(const __half* __restrict__ a_hi, const __half* __restrict__ a_lo,
                     const __half* __restrict__ w,
                     const float* __restrict__ bias, float* __restrict__ C)
{
    extern __shared__ char smem[];
    const uint32_t sb0 = smem_u32(smem);

    const int tid  = threadIdx.x;
    const int lane = tid & 31;
    const int wid  = tid >> 5;
    const int warpM = (wid >> 2) * 64;
    const int warpN = (wid & 3) * 32;
    const int blockRow = blockIdx.y * 128;
    const int blockCol = blockIdx.x * 128;

    const int ldRow0 = tid >> 2;
    const int ldQ    = (tid & 3) * 16;
    const int lmRow = lane & 15;
    const int lmK   = (lane >> 4) * 8;

    float acc[4][4][4];
#pragma unroll
    for (int mt = 0; mt < 4; mt++)
#pragma unroll
        for (int nt = 0; nt < 4; nt++)
#pragma unroll
            for (int r = 0; r < 4; r++) acc[mt][nt][r] = 0.0f;

    auto load_stage = [&](int stage, int chunk) {
        const int k0 = chunk * 32;
        const uint32_t sb = sb0 + stage * PSTAGE;
#pragma unroll
        for (int j = 0; j < 2; j++) {
            int row = ldRow0 + j * 64;
            uint32_t so = (uint32_t)(row * 80) + ldQ;
            CP16(sb + OFF_AH + so, &a_hi[(size_t)(blockRow + row) * D_MODEL + k0] + ldQ / 2);
            CP16(sb + OFF_AL + so, &a_lo[(size_t)(blockRow + row) * D_MODEL + k0] + ldQ / 2);
            CP16(sb + OFF_BH + so, &w[(size_t)(blockCol + row) * D_MODEL + k0] + ldQ / 2);
        }
        CP_COMMIT();
    };

    load_stage(0, 0);

    for (int chunk = 0; chunk < 32; chunk++) {
        if (chunk < 31) { load_stage((chunk + 1) & 1, chunk + 1); CP_WAIT1(); }
        else           { CP_WAIT0(); }
        __syncthreads();

        const uint32_t sb = sb0 + (chunk & 1) * PSTAGE;
        const uint32_t aAddrBase = sb + (uint32_t)(((warpM + lmRow) * SPAD + lmK) * 2);
        const uint32_t bAddrBase = sb + (uint32_t)(((warpN + lmRow) * SPAD + lmK) * 2);

#pragma unroll
        for (int ks = 0; ks < 2; ks++) {
            const uint32_t kOff = (uint32_t)(ks * 16 * 2);
            uint32_t aH[4][4], aL[4][4], bH[4][2];
#pragma unroll
            for (int mt = 0; mt < 4; mt++) {
                uint32_t ad = aAddrBase + kOff + (uint32_t)(mt * 16 * SPAD * 2);
                LDSM4(aH[mt][0], aH[mt][1], aH[mt][2], aH[mt][3], ad + OFF_AH);
                LDSM4(aL[mt][0], aL[mt][1], aL[mt][2], aL[mt][3], ad + OFF_AL);
            }
#pragma unroll
            for (int ntp = 0; ntp < 2; ntp++) {
                uint32_t bd = bAddrBase + kOff + (uint32_t)(ntp * 16 * SPAD * 2);
                uint32_t r0, r1, r2, r3;
                LDSM4(r0, r1, r2, r3, bd + OFF_BH);
                bH[2 * ntp][0] = r0; bH[2 * ntp + 1][0] = r1;
                bH[2 * ntp][1] = r2; bH[2 * ntp + 1][1] = r3;
            }
#pragma unroll
            for (int mt = 0; mt < 4; mt++)
#pragma unroll
                for (int nt = 0; nt < 4; nt++) {
                    MMAH(acc[mt][nt], aH[mt], bH[nt]);
                    MMAH(acc[mt][nt], aL[mt], bH[nt]);
                }
        }
        __syncthreads();
    }

#pragma unroll
    for (int mt = 0; mt < 4; mt++) {
#pragma unroll
        for (int nt = 0; nt < 4; nt++) {
            int row0 = blockRow + warpM + mt * 16 + (lane >> 2);
            int col  = blockCol + warpN + nt * 8 + (lane & 3) * 2;
            float b0 = bias[col], b1 = bias[col + 1];
#pragma unroll
            for (int half = 0; half < 2; half++) {
                int r = row0 + half * 8;
                float2 v = {acc[mt][nt][half * 2 + 0] + b0, acc[mt][nt][half * 2 + 1] + b1};
                *(float2*)&C[(size_t)r * D_MODEL + col] = v;
            }
        }
    }
}

// ==================== scores: 128x64 tiles, 3 CTAs/SM ========================
#define QPAD 72
#define SC_OFF_K 18432        // 128*72*2
#define SC_SMEM  27648        // + 64*72*2

__global__ __launch_bounds__(256, 3)
void scores_mma_kernel(const __half* __restrict__ qf, const __half* __restrict__ kf,
                       const float* __restrict__ mask, __half* __restrict__ eout,
                       float* __restrict__ rowsum)
{
    extern __shared__ char sm[];
    const uint32_t sq = smem_u32(sm);
    __half* sQ = (__half*)sm;
    __half* sK = (__half*)(sm + SC_OFF_K);

    const int z = blockIdx.z;
    const int b = z / NUM_HEADS;
    const int tid = threadIdx.x, lane = tid & 31, wid = tid >> 5;
    const int warpM = (wid >> 2) * 64;          // {0, 64}
    const int warpN = (wid & 3) * 16;           // {0, 16, 32, 48}
    const int blockRow = blockIdx.y * 128, blockCol = blockIdx.x * 64;
    const int lmRow = lane & 15, lmK = (lane >> 4) * 8;

    // load q 128x64 (4 uint4/thread), k 64x64 (2 uint4/thread)
#pragma unroll
    for (int i = 0; i < 4; i++) {
        int id = tid + i * 256;
        int row = id >> 3, q = id & 7;
        *(uint4*)&sQ[row * QPAD + q * 8] =
            *(const uint4*)&qf[((size_t)z * SS + blockRow + row) * DEPTH + q * 8];
    }
#pragma unroll
    for (int i = 0; i < 2; i++) {
        int id = tid + i * 256;
        int row = id >> 3, q = id & 7;
        *(uint4*)&sK[row * QPAD + q * 8] =
            *(const uint4*)&kf[((size_t)z * SS + blockCol + row) * DEPTH + q * 8];
    }
    __syncthreads();

    float acc[4][2][4];
#pragma unroll
    for (int mt = 0; mt < 4; mt++)
#pragma unroll
        for (int nt = 0; nt < 2; nt++)
#pragma unroll
            for (int r = 0; r < 4; r++) acc[mt][nt][r] = 0.0f;

    const uint32_t aBase = sq + (uint32_t)(((warpM + lmRow) * QPAD + lmK) * 2);
    const uint32_t bBase = sq + SC_OFF_K + (uint32_t)(((warpN + lmRow) * QPAD + lmK) * 2);

#pragma unroll
    for (int ks = 0; ks < 4; ks++) {
        const uint32_t kOff = (uint32_t)(ks * 16 * 2);
        uint32_t aH[4][4], bH[2][2];
#pragma unroll
        for (int mt = 0; mt < 4; mt++) {
            uint32_t ad = aBase + kOff + (uint32_t)(mt * 16 * QPAD * 2);
            LDSM4(aH[mt][0], aH[mt][1], aH[mt][2], aH[mt][3], ad);
        }
        {
            uint32_t r0, r1, r2, r3;
            LDSM4(r0, r1, r2, r3, bBase + kOff);
            bH[0][0] = r0; bH[1][0] = r1;
            bH[0][1] = r2; bH[1][1] = r3;
        }
#pragma unroll
        for (int mt = 0; mt < 4; mt++)
#pragma unroll
            for (int nt = 0; nt < 2; nt++)
                MMAH(acc[mt][nt], aH[mt], bH[nt]);
    }

    float mcol[2][2];
#pragma unroll
    for (int nt = 0; nt < 2; nt++) {
        int col = blockCol + warpN + nt * 8 + (lane & 3) * 2;
        mcol[nt][0] = mask[(size_t)b * SS + col]     * (-1e9f);
        mcol[nt][1] = mask[(size_t)b * SS + col + 1] * (-1e9f);
    }

    __syncthreads();
    __half* sE = (__half*)sm;     // 128 x QPAD stride

#pragma unroll
    for (int mt = 0; mt < 4; mt++) {
#pragma unroll
        for (int half = 0; half < 2; half++) {
            int lrow = warpM + mt * 16 + (lane >> 2) + half * 8;
            float rs = 0.0f;
#pragma unroll
            for (int nt = 0; nt < 2; nt++) {
                int lcol = warpN + nt * 8 + (lane & 3) * 2;
                float e0 = __expf(acc[mt][nt][half * 2 + 0] * 0.125f + mcol[nt][0]);
                float e1 = __expf(acc[mt][nt][half * 2 + 1] * 0.125f + mcol[nt][1]);
                rs += e0 + e1;
                *(__half2*)&sE[lrow * QPAD + lcol] = __floats2half2_rn(e0, e1);
            }
            rs += __shfl_xor_sync(0xffffffffu, rs, 1);
            rs += __shfl_xor_sync(0xffffffffu, rs, 2);
            if ((lane & 3) == 0)
                rowsum[((size_t)z * SS + blockRow + lrow) * RS_W + blockIdx.x * 4 + (wid & 3)] = rs;
        }
    }
    __syncthreads();

    __half* Ez = eout + (size_t)z * SS * SS;
#pragma unroll
    for (int i = 0; i < 4; i++) {
        int id = tid + i * 256;
        int row = id >> 3, q = id & 7;
        *(uint4*)&Ez[(size_t)(blockRow + row) * SS + blockCol + q * 8] =
            *(const uint4*)&sE[row * QPAD + q * 8];
    }
}

// ==================== AV: cp.async pipelined, single-fp16 V ==================
#define AVPAD 72
#define AV_STAGE   46080      // A 256*72*2 + B 64*72*2
#define AV_OFF_B   36864
#define AV_OFF_INV 92160      // after 2 stages
#define AV_SMEM    93184      // + 256*4

__global__ __launch_bounds__(256, 2)
void av_mma_kernel(const __half* __restrict__ e, const __half* __restrict__ vt,
                   const float* __restrict__ rowsum, float* __restrict__ attn,
                   __half* __restrict__ o_hi, __half* __restrict__ o_lo)
{
    extern __shared__ char avsm[];
    const uint32_t sb0 = smem_u32(avsm);
    float* invs = (float*)(avsm + AV_OFF_INV);

    const int z = blockIdx.y;
    const int b = z / NUM_HEADS, h = z % NUM_HEADS;
    const int rowbase = blockIdx.x * 256;
    const int tid = threadIdx.x, lane = tid & 31, wid = tid >> 5;
    const int warpM = wid * 32;
    const int lmRow = lane & 15, lmK = (lane >> 4) * 8;

    {
        const float* rp = &rowsum[((size_t)z * SS + rowbase + tid) * RS_W];
        float s = 0.0f;
#pragma unroll
        for (int j = 0; j < RS_W; j++) s += rp[j];
        invs[tid] = 1.0f / s;
    }
    __syncthreads();

    const __half* Ez = e + (size_t)z * SS * SS;
    float* Az = attn + (size_t)z * SS * SS;

    auto load_stage = [&](int stage, int chunk) {
        const int k0 = chunk * 64;
        const uint32_t sb = sb0 + stage * AV_STAGE;
#pragma unroll
        for (int i = 0; i < 8; i++) {
            int id = tid + i * 256;
            int row = id >> 3, q = id & 7;
            CP16(sb + (uint32_t)(row * 144 + q * 16),
                 &Ez[(size_t)(rowbase + row) * SS + k0 + q * 8]);
        }
#pragma unroll
        for (int i = 0; i < 2; i++) {
            int id = tid + i * 256;
            int row = id >> 3, q = id & 7;
            CP16(sb + AV_OFF_B + (uint32_t)(row * 144 + q * 16),
                 &vt[((size_t)z * DEPTH + row) * SS + k0 + q * 8]);
        }
        CP_COMMIT();
    };

    float acc[2][8][4];
#pragma unroll
    for (int mt = 0; mt < 2; mt++)
#pragma unroll
        for (int nt = 0; nt < 8; nt++)
#pragma unroll
            for (int r = 0; r < 4; r++) acc[mt][nt][r] = 0.0f;

    load_stage(0, 0);

    for (int chunk = 0; chunk < 32; chunk++) {
        if (chunk < 31) { load_stage((chunk + 1) & 1, chunk + 1); CP_WAIT1(); }
        else           { CP_WAIT0(); }
        __syncthreads();

        const uint32_t sb = sb0 + (chunk & 1) * AV_STAGE;
        const __half* sA = (const __half*)(avsm + (chunk & 1) * AV_STAGE);
        const uint32_t aBase = sb + (uint32_t)(((warpM + lmRow) * AVPAD + lmK) * 2);
        const uint32_t bBase = sb + AV_OFF_B + (uint32_t)((lmRow * AVPAD + lmK) * 2);

        // normalize + attn write FIRST (stores drain under the MMA work)
        const int k0 = chunk * 64;
#pragma unroll
        for (int i = 0; i < 8; i++) {
            int id = tid + i * 256;
            int row = id >> 3, q = id & 7;
            uint4 ev = *(const uint4*)&sA[row * AVPAD + q * 8];
            const float inv = invs[row];
            const __half2* hp = (const __half2*)&ev;
            float2 f0 = __half22float2(hp[0]);
            float2 f1 = __half22float2(hp[1]);
            float2 f2 = __half22float2(hp[2]);
            float2 f3 = __half22float2(hp[3]);
            float4 v0 = {f0.x * inv, f0.y * inv, f1.x * inv, f1.y * inv};
            float4 v1 = {f2.x * inv, f2.y * inv, f3.x * inv, f3.y * inv};
            size_t ao = (size_t)(rowbase + row) * SS + k0 + q * 8;
            *(float4*)&Az[ao]     = v0;
            *(float4*)&Az[ao + 4] = v1;
        }

#pragma unroll
        for (int ks = 0; ks < 4; ks++) {
            const uint32_t kOff = (uint32_t)(ks * 16 * 2);
            uint32_t aF[2][4], bH[8][2];
#pragma unroll
            for (int mt = 0; mt < 2; mt++) {
                uint32_t ad = aBase + kOff + (uint32_t)(mt * 16 * AVPAD * 2);
                LDSM4(aF[mt][0], aF[mt][1], aF[mt][2], aF[mt][3], ad);
            }
#pragma unroll
            for (int ntp = 0; ntp < 4; ntp++) {
                uint32_t bd = bBase + kOff + (uint32_t)(ntp * 16 * AVPAD * 2);
                uint32_t r0, r1, r2, r3;
                LDSM4(r0, r1, r2, r3, bd);
                bH[2 * ntp][0] = r0; bH[2 * ntp + 1][0] = r1;
                bH[2 * ntp][1] = r2; bH[2 * ntp + 1][1] = r3;
            }
#pragma unroll
            for (int mt = 0; mt < 2; mt++)
#pragma unroll
                for (int nt = 0; nt < 8; nt++)
                    MMAH(acc[mt][nt], aF[mt], bH[nt]);
        }
        __syncthreads();
    }

#pragma unroll
    for (int mt = 0; mt < 2; mt++) {
#pragma unroll
        for (int nt = 0; nt < 8; nt++) {
            int lrow0 = warpM + mt * 16 + (lane >> 2);
            int col   = nt * 8 + (lane & 3) * 2;
#pragma unroll
            for (int half = 0; half < 2; half++) {
                int lr = lrow0 + half * 8;
                float inv = invs[lr];
                int r = rowbase + lr;
                float vx = acc[mt][nt][half * 2 + 0] * inv;
                float vy = acc[mt][nt][half * 2 + 1] * inv;
                size_t o = ((size_t)b * SS + r) * D_MODEL + h * DEPTH + col;
                __half hx = __float2half(vx);
                __half hy = __float2half(vy);
                __half2 hp = {hx, hy};
                *(__half2*)&o_hi[o] = hp;
                __half2 lp = {__float2half(vx - __half2float(hx)),
                              __float2half(vy - __half2float(hy))};
                *(__half2*)&o_lo[o] = lp;
            }
        }
    }
}

// =====================================================================
extern "C" void kernel_launch(void* const* d_in, const int* in_sizes, int n_in,
                              void* d_out, int out_size)
{
    const float* Q    = (const float*)d_in[0];
    const float* K    = (const float*)d_in[1];
    const float* V    = (const float*)d_in[2];
    const float* mask = (const float*)d_in[3];
    const float* Wq   = (const float*)d_in[4];
    const float* bq   = (const float*)d_in[5];
    const float* Wk   = (const float*)d_in[6];
    const float* bk   = (const float*)d_in[7];
    const float* Wv   = (const float*)d_in[8];
    const float* bv   = (const float*)d_in[9];
    const float* Wo   = (const float*)d_in[10];
    const float* bo   = (const float*)d_in[11];

    float* out = (float*)d_out;

    float *rowsum, *attn;
    __half *inb, *w, *qf, *kf, *vt, *ohi, *olo, *ebuf;
    cudaGetSymbolAddress((void**)&rowsum, g_rowsum);
    cudaGetSymbolAddress((void**)&ebuf, g_e);
    cudaGetSymbolAddress((void**)&inb, g_in);
    cudaGetSymbolAddress((void**)&w, g_w);
    cudaGetSymbolAddress((void**)&qf, g_q_f);
    cudaGetSymbolAddress((void**)&kf, g_k_f);
    cudaGetSymbolAddress((void**)&vt, g_vt);
    cudaGetSymbolAddress((void**)&ohi, g_o_hi);
    cudaGetSymbolAddress((void**)&olo, g_o_lo);

    if ((size_t)out_size >= OUT_ELEMS + ATTN_ELEMS) {
        attn = out + OUT_ELEMS;
    } else {
        cudaGetSymbolAddress((void**)&attn, g_attn_fallback);
    }

    static bool attr_done = false;
    if (!attr_done) {
        cudaFuncSetAttribute(proj_qkv_kernel, cudaFuncAttributeMaxDynamicSharedMemorySize, 2 * P2STAGE);
        cudaFuncSetAttribute(proj_out_kernel, cudaFuncAttributeMaxDynamicSharedMemorySize, 2 * PSTAGE);
        cudaFuncSetAttribute(scores_mma_kernel, cudaFuncAttributeMaxDynamicSharedMemorySize, SC_SMEM);
        cudaFuncSetAttribute(av_mma_kernel, cudaFuncAttributeMaxDynamicSharedMemorySize, AV_SMEM);
        attr_done = true;
    }

    // 1. splits
    dim3 wtBlock(32, 8);
    split_w4_kernel<<<dim3(32, 32, 4), wtBlock>>>(Wq, Wk, Wv, Wo, w);
    split_in3_kernel<<<dim3(NELEM / 256, 3), 256>>>(Q, K, V, inb);

    // 2. QKV projections
    proj_qkv_kernel<<<dim3(8, 32, 3), 256, 2 * P2STAGE>>>(
        inb, w, bq, bk, bv, qf, kf, vt);

    // 3. scores (128x64 tiles, 3 CTA/SM) -> e fp16 + rowsum partials
    scores_mma_kernel<<<dim3(32, 16, NZ), 256, SC_SMEM>>>(
        qf, kf, mask, ebuf, rowsum);

    // 4. AV (cp.async pipelined) + fused attn normalize
    av_mma_kernel<<<dim3(8, NZ), 256, AV_SMEM>>>(ebuf, vt, rowsum, attn, ohi, olo);

    // 5. output projection
    proj_out_kernel<<<dim3(8, 32), 256, 2 * PSTAGE>>>(
        ohi, olo, w + (size_t)3 * WELEM, bo, out);
}

// round 15
// speedup vs baseline: 1.1304x; 1.1304x over previous
#include <cuda_runtime.h>
#include <cuda_bf16.h>
#include <cuda_fp16.h>
#include <cstdint>
#include <math.h>

#define D_MODEL   1024
#define NUM_HEADS 16
#define DEPTH     64
#define BB        2
#define SS        2048
#define MROWS     (BB * SS)                              // 4096
#define ATTN_ELEMS ((size_t)BB * NUM_HEADS * SS * SS)    // 134,217,728
#define OUT_ELEMS  ((size_t)MROWS * D_MODEL)             // 4,194,304
#define NZ        (BB * NUM_HEADS)                       // 32
#define RS_W      64
#define NELEM     (MROWS * D_MODEL)                      // 4,194,304
#define WELEM     (D_MODEL * D_MODEL)                    // 1,048,576

// ---------------- scratch (static device globals; no allocations) ------------
__device__ float g_rowsum[(size_t)NZ * SS * RS_W];
__device__ __half g_e[ATTN_ELEMS];                       // unnormalized exp
__device__ __half g_in[3 * (size_t)NELEM];               // QKV inputs fp16
__device__ __half g_w[4 * (size_t)WELEM];                // Wq,Wk,Wv,Wo [n][k] fp16
__device__ __half g_q_f[(size_t)NZ * SS * DEPTH];        // [z,s,d] fp16
__device__ __half g_k_f[(size_t)NZ * SS * DEPTH];        // [z,s,d] fp16
__device__ __half g_vt[(size_t)NZ * SS * DEPTH];         // [z,d,s] fp16 single
__device__ __half g_o_f[(size_t)NELEM];                  // O fp16 single
__device__ float g_attn_fallback[ATTN_ELEMS];

// ============================ PTX helpers ====================================
#define MMAH(d, a, b)                                                         \
    asm volatile("mma.sync.aligned.m16n8k16.row.col.f32.f16.f16.f32 "         \
        "{%0,%1,%2,%3}, {%4,%5,%6,%7}, {%8,%9}, {%0,%1,%2,%3};"               \
        : "+f"((d)[0]), "+f"((d)[1]), "+f"((d)[2]), "+f"((d)[3])              \
        : "r"((a)[0]), "r"((a)[1]), "r"((a)[2]), "r"((a)[3]),                 \
          "r"((b)[0]), "r"((b)[1]))

#define LDSM4(R0, R1, R2, R3, ADDR)                                           \
    asm volatile("ldmatrix.sync.aligned.m8n8.x4.shared.b16 {%0,%1,%2,%3}, [%4];" \
        : "=r"(R0), "=r"(R1), "=r"(R2), "=r"(R3) : "r"(ADDR))

#define CP16(SADDR, GPTR)                                                     \
    asm volatile("cp.async.cg.shared.global [%0], [%1], 16;"                  \
        :: "r"(SADDR), "l"(GPTR))
#define CP_COMMIT() asm volatile("cp.async.commit_group;" ::: "memory")
#define CP_WAIT1()  asm volatile("cp.async.wait_group 1;" ::: "memory")
#define CP_WAIT0()  asm volatile("cp.async.wait_group 0;" ::: "memory")

__device__ __forceinline__ uint32_t smem_u32(const void* p) {
    uint32_t a;
    asm("{ .reg .u64 t; cvta.to.shared.u64 t, %1; cvt.u32.u64 %0, t; }" : "=r"(a) : "l"(p));
    return a;
}

// ============================ split kernels ==================================
__global__ __launch_bounds__(256)
void split_in3_kernel(const float* __restrict__ Q, const float* __restrict__ K,
                      const float* __restrict__ V, __half* __restrict__ dst)
{
    int z = blockIdx.y;
    const float* A = (z == 0) ? Q : (z == 1) ? K : V;
    size_t i = (size_t)blockIdx.x * 256 + threadIdx.x;
    dst[(size_t)z * NELEM + i] = __float2half(A[i]);
}

__global__ __launch_bounds__(256)
void split_w4_kernel(const float* __restrict__ W0, const float* __restrict__ W1,
                     const float* __restrict__ W2, const float* __restrict__ W3,
                     __half* __restrict__ wt)
{
    __shared__ float t[32][33];
    int z = blockIdx.z;
    const float* W = (z == 0) ? W0 : (z == 1) ? W1 : (z == 2) ? W2 : W3;
    int tx = threadIdx.x, ty = threadIdx.y;
    int n0 = blockIdx.x * 32, k0 = blockIdx.y * 32;
#pragma unroll
    for (int j = 0; j < 4; j++)
        t[ty + j * 8][tx] = W[(size_t)(k0 + ty + j * 8) * D_MODEL + n0 + tx];
    __syncthreads();
#pragma unroll
    for (int j = 0; j < 4; j++) {
        size_t o = (size_t)z * WELEM + (size_t)(n0 + ty + j * 8) * D_MODEL + k0 + tx;
        wt[o] = __float2half(t[tx][ty + j * 8]);
    }
}

// ==================== GEMM core: fp16 x fp16, K-chunk 64, 128x128 ============
// MODE 0..2: QKV epilogues (q fp16 / k fp16 / v transposed fp16)
// MODE 3:    fp32 row-major output with bias (final projection)
#define P2PAD 72
#define P2STAGE 36864     // 2 arrays * 128*72*2
#define P2_OFF_A 0
#define P2_OFF_B 18432

template <int MODE>
__device__ __forceinline__ void gemm_fp16_core(
    const __half* __restrict__ a, const __half* __restrict__ wh,
    const float* __restrict__ bias, char* smem,
    int blockRow, int blockCol,
    __half* __restrict__ out_h, float* __restrict__ out_f)
{
    const uint32_t sb0 = smem_u32(smem);
    const int tid  = threadIdx.x;
    const int lane = tid & 31;
    const int wid  = tid >> 5;
    const int warpM = (wid >> 2) * 64;
    const int warpN = (wid & 3) * 32;
    const int lmRow = lane & 15;
    const int lmK   = (lane >> 4) * 8;

    float acc[4][4][4];
#pragma unroll
    for (int mt = 0; mt < 4; mt++)
#pragma unroll
        for (int nt = 0; nt < 4; nt++)
#pragma unroll
            for (int r = 0; r < 4; r++) acc[mt][nt][r] = 0.0f;

    auto load_stage = [&](int stage, int chunk) {
        const int k0 = chunk * 64;
        const uint32_t sb = sb0 + stage * P2STAGE;
#pragma unroll
        for (int j = 0; j < 4; j++) {
            int id = tid + j * 256;
            int row = id >> 3, q = id & 7;
            uint32_t so = (uint32_t)(row * 144 + q * 16);
            CP16(sb + P2_OFF_A + so, &a[(size_t)(blockRow + row) * D_MODEL + k0 + q * 8]);
            CP16(sb + P2_OFF_B + so, &wh[(size_t)(blockCol + row) * D_MODEL + k0 + q * 8]);
        }
        CP_COMMIT();
    };

    load_stage(0, 0);

    for (int chunk = 0; chunk < 16; chunk++) {
        if (chunk < 15) { load_stage((chunk + 1) & 1, chunk + 1); CP_WAIT1(); }
        else           { CP_WAIT0(); }
        __syncthreads();

        const uint32_t sb = sb0 + (chunk & 1) * P2STAGE;
        const uint32_t aBase = sb + P2_OFF_A + (uint32_t)(((warpM + lmRow) * P2PAD + lmK) * 2);
        const uint32_t bBase = sb + P2_OFF_B + (uint32_t)(((warpN + lmRow) * P2PAD + lmK) * 2);

#pragma unroll
        for (int ks = 0; ks < 4; ks++) {
            const uint32_t kOff = (uint32_t)(ks * 16 * 2);
            uint32_t aF[4][4], bH[4][2];
#pragma unroll
            for (int mt = 0; mt < 4; mt++) {
                uint32_t ad = aBase + kOff + (uint32_t)(mt * 16 * P2PAD * 2);
                LDSM4(aF[mt][0], aF[mt][1], aF[mt][2], aF[mt][3], ad);
            }
#pragma unroll
            for (int ntp = 0; ntp < 2; ntp++) {
                uint32_t bd = bBase + kOff + (uint32_t)(ntp * 16 * P2PAD * 2);
                uint32_t r0, r1, r2, r3;
                LDSM4(r0, r1, r2, r3, bd);
                bH[2 * ntp][0] = r0; bH[2 * ntp + 1][0] = r1;
                bH[2 * ntp][1] = r2; bH[2 * ntp + 1][1] = r3;
            }
#pragma unroll
            for (int mt = 0; mt < 4; mt++)
#pragma unroll
                for (int nt = 0; nt < 4; nt++)
                    MMAH(acc[mt][nt], aF[mt], bH[nt]);
        }
        __syncthreads();
    }

#pragma unroll
    for (int mt = 0; mt < 4; mt++) {
#pragma unroll
        for (int nt = 0; nt < 4; nt++) {
            int row0 = blockRow + warpM + mt * 16 + (lane >> 2);
            int col  = blockCol + warpN + nt * 8 + (lane & 3) * 2;
            float b0 = bias[col], b1 = bias[col + 1];
#pragma unroll
            for (int half = 0; half < 2; half++) {
                int r = row0 + half * 8;
                float vx = acc[mt][nt][half * 2 + 0] + b0;
                float vy = acc[mt][nt][half * 2 + 1] + b1;
                if (MODE == 3) {
                    float2 v = {vx, vy};
                    *(float2*)&out_f[(size_t)r * D_MODEL + col] = v;
                } else {
                    int z = (r >> 11) * NUM_HEADS + (col >> 6);
                    int s = r & (SS - 1);
                    int d = col & (DEPTH - 1);
                    if (MODE == 0 || MODE == 1) {
                        size_t o = ((size_t)z * SS + s) * DEPTH + d;
                        __half2 hp = {__float2half(vx), __float2half(vy)};
                        *(__half2*)&out_h[o] = hp;
                    } else {
                        size_t o = ((size_t)z * DEPTH + d) * SS + s;
                        out_h[o]      = __float2half(vx);
                        out_h[o + SS] = __float2half(vy);
                    }
                }
            }
        }
    }
}

__global__ __launch_bounds__(256, 2)
void proj_qkv_kernel(const __half* __restrict__ in, const __half* __restrict__ w,
                     const float* __restrict__ bq, const float* __restrict__ bk,
                     const float* __restrict__ bv,
                     __half* __restrict__ qf, __half* __restrict__ kf,
                     __half* __restrict__ vt)
{
    extern __shared__ char smem[];
    const int zz = blockIdx.z;
    const __half* a  = in + (size_t)zz * NELEM;
    const __half* wh = w + (size_t)zz * WELEM;
    if (zz == 0)
        gemm_fp16_core<0>(a, wh, bq, smem, blockIdx.y * 128, blockIdx.x * 128, qf, nullptr);
    else if (zz == 1)
        gemm_fp16_core<1>(a, wh, bk, smem, blockIdx.y * 128, blockIdx.x * 128, kf, nullptr);
    else
        gemm_fp16_core<2>(a, wh, bv, smem, blockIdx.y * 128, blockIdx.x * 128, vt, nullptr);
}

__global__ __launch_bounds__(256, 2)
void proj_out_kernel(const __half* __restrict__ of, const __half* __restrict__ w,
                     const float* __restrict__ bias, float* __restrict__ C)
{
    extern __shared__ char smem[];
    gemm_fp16_core<3>(of, w, bias, smem, blockIdx.y * 128, blockIdx.x * 128, nullptr, C);
}

// ==================== scores: single-fp16 mma -> e fp16 (staged) =============
#define QPAD 72
#define EPAD 136

__global__ __launch_bounds__(256, 2)
void scores_mma_kernel(const __half* __restrict__ qf, const __half* __restrict__ kf,
                       const float* __restrict__ mask, __half* __restrict__ eout,
                       float* __restrict__ rowsum)
{
    extern __shared__ char sm[];
    const uint32_t sq = smem_u32(sm);
    __half* sQh = (__half*)sm;
    __half* sKh = sQh + 128 * QPAD;
    const uint32_t OQH = 0, OKH = 128 * QPAD * 2;

    const int z = blockIdx.z;
    const int b = z / NUM_HEADS;
    const int tid = threadIdx.x, lane = tid & 31, wid = tid >> 5;
    const int warpM = (wid >> 2) * 64, warpN = (wid & 3) * 32;
    const int blockRow = blockIdx.y * 128, blockCol = blockIdx.x * 128;
    const int lmRow = lane & 15, lmK = (lane >> 4) * 8;

#pragma unroll
    for (int i = 0; i < 4; i++) {
        int id = tid + i * 256;
        int row = id >> 3, q = id & 7;
        size_t gq = ((size_t)z * SS + blockRow + row) * DEPTH + q * 8;
        size_t gk = ((size_t)z * SS + blockCol + row) * DEPTH + q * 8;
        int so = row * QPAD + q * 8;
        *(uint4*)&sQh[so] = *(const uint4*)&qf[gq];
        *(uint4*)&sKh[so] = *(const uint4*)&kf[gk];
    }
    __syncthreads();

    float acc[4][4][4];
#pragma unroll
    for (int mt = 0; mt < 4; mt++)
#pragma unroll
        for (int nt = 0; nt < 4; nt++)
#pragma unroll
            for (int r = 0; r < 4; r++) acc[mt][nt][r] = 0.0f;

    const uint32_t aAddrBase = sq + (uint32_t)(((warpM + lmRow) * QPAD + lmK) * 2);
    const uint32_t bAddrBase = sq + (uint32_t)(((warpN + lmRow) * QPAD + lmK) * 2);

#pragma unroll
    for (int ks = 0; ks < 4; ks++) {
        const uint32_t kOff = (uint32_t)(ks * 16 * 2);
        uint32_t aH[4][4], bH[4][2];
#pragma unroll
        for (int mt = 0; mt < 4; mt++) {
            uint32_t ad = aAddrBase + kOff + (uint32_t)(mt * 16 * QPAD * 2);
            LDSM4(aH[mt][0], aH[mt][1], aH[mt][2], aH[mt][3], ad + OQH);
        }
#pragma unroll
        for (int ntp = 0; ntp < 2; ntp++) {
            uint32_t bd = bAddrBase + kOff + (uint32_t)(ntp * 16 * QPAD * 2);
            uint32_t r0, r1, r2, r3;
            LDSM4(r0, r1, r2, r3, bd + OKH);
            bH[2 * ntp][0] = r0; bH[2 * ntp + 1][0] = r1;
            bH[2 * ntp][1] = r2; bH[2 * ntp + 1][1] = r3;
        }
#pragma unroll
        for (int mt = 0; mt < 4; mt++)
#pragma unroll
            for (int nt = 0; nt < 4; nt++)
                MMAH(acc[mt][nt], aH[mt], bH[nt]);
    }

    float mcol[4][2];
#pragma unroll
    for (int nt = 0; nt < 4; nt++) {
        int col = blockCol + warpN + nt * 8 + (lane & 3) * 2;
        mcol[nt][0] = mask[(size_t)b * SS + col]     * (-1e9f);
        mcol[nt][1] = mask[(size_t)b * SS + col + 1] * (-1e9f);
    }

    __syncthreads();
    __half* sE = (__half*)sm;

#pragma unroll
    for (int mt = 0; mt < 4; mt++) {
#pragma unroll
        for (int half = 0; half < 2; half++) {
            int lrow = warpM + mt * 16 + (lane >> 2) + half * 8;
            float rs = 0.0f;
#pragma unroll
            for (int nt = 0; nt < 4; nt++) {
                int lcol = warpN + nt * 8 + (lane & 3) * 2;
                float e0 = __expf(acc[mt][nt][half * 2 + 0] * 0.125f + mcol[nt][0]);
                float e1 = __expf(acc[mt][nt][half * 2 + 1] * 0.125f + mcol[nt][1]);
                rs += e0 + e1;
                *(__half2*)&sE[lrow * EPAD + lcol] = __floats2half2_rn(e0, e1);
            }
            rs += __shfl_xor_sync(0xffffffffu, rs, 1);
            rs += __shfl_xor_sync(0xffffffffu, rs, 2);
            if ((lane & 3) == 0)
                rowsum[((size_t)z * SS + blockRow + lrow) * RS_W + blockIdx.x * 4 + (wid & 3)] = rs;
        }
    }
    __syncthreads();

    __half* Ez = eout + (size_t)z * SS * SS;
#pragma unroll
    for (int i = 0; i < 8; i++) {
        int id = tid + i * 256;
        int row = id >> 4, q = id & 15;
        *(uint4*)&Ez[(size_t)(blockRow + row) * SS + blockCol + q * 8] =
            *(const uint4*)&sE[row * EPAD + q * 8];
    }
}

// ==================== AV: cp.async pipelined, single-fp16 V ==================
#define AVPAD 72
#define AV_STAGE   46080      // A 256*72*2 + B 64*72*2
#define AV_OFF_B   36864
#define AV_OFF_INV 92160      // after 2 stages
#define AV_SMEM    93184      // + 256*4

__global__ __launch_bounds__(256, 2)
void av_mma_kernel(const __half* __restrict__ e, const __half* __restrict__ vt,
                   const float* __restrict__ rowsum, float* __restrict__ attn,
                   __half* __restrict__ of)
{
    extern __shared__ char avsm[];
    const uint32_t sb0 = smem_u32(avsm);
    float* invs = (float*)(avsm + AV_OFF_INV);

    const int z = blockIdx.y;
    const int b = z / NUM_HEADS, h = z % NUM_HEADS;
    const int rowbase = blockIdx.x * 256;
    const int tid = threadIdx.x, lane = tid & 31, wid = tid >> 5;
    const int warpM = wid * 32;
    const int lmRow = lane & 15, lmK = (lane >> 4) * 8;

    {
        const float* rp = &rowsum[((size_t)z * SS + rowbase + tid) * RS_W];
        float s = 0.0f;
#pragma unroll
        for (int j = 0; j < RS_W; j++) s += rp[j];
        invs[tid] = 1.0f / s;
    }
    __syncthreads();

    const __half* Ez = e + (size_t)z * SS * SS;
    float* Az = attn + (size_t)z * SS * SS;

    auto load_stage = [&](int stage, int chunk) {
        const int k0 = chunk * 64;
        const uint32_t sb = sb0 + stage * AV_STAGE;
#pragma unroll
        for (int i = 0; i < 8; i++) {
            int id = tid + i * 256;
            int row = id >> 3, q = id & 7;
            CP16(sb + (uint32_t)(row * 144 + q * 16),
                 &Ez[(size_t)(rowbase + row) * SS + k0 + q * 8]);
        }
#pragma unroll
        for (int i = 0; i < 2; i++) {
            int id = tid + i * 256;
            int row = id >> 3, q = id & 7;
            CP16(sb + AV_OFF_B + (uint32_t)(row * 144 + q * 16),
                 &vt[((size_t)z * DEPTH + row) * SS + k0 + q * 8]);
        }
        CP_COMMIT();
    };

    float acc[2][8][4];
#pragma unroll
    for (int mt = 0; mt < 2; mt++)
#pragma unroll
        for (int nt = 0; nt < 8; nt++)
#pragma unroll
            for (int r = 0; r < 4; r++) acc[mt][nt][r] = 0.0f;

    load_stage(0, 0);

    for (int chunk = 0; chunk < 32; chunk++) {
        if (chunk < 31) { load_stage((chunk + 1) & 1, chunk + 1); CP_WAIT1(); }
        else           { CP_WAIT0(); }
        __syncthreads();

        const uint32_t sb = sb0 + (chunk & 1) * AV_STAGE;
        const __half* sA = (const __half*)(avsm + (chunk & 1) * AV_STAGE);
        const uint32_t aBase = sb + (uint32_t)(((warpM + lmRow) * AVPAD + lmK) * 2);
        const uint32_t bBase = sb + AV_OFF_B + (uint32_t)((lmRow * AVPAD + lmK) * 2);

        // MMA first (tensor pipe starts immediately)
#pragma unroll
        for (int ks = 0; ks < 4; ks++) {
            const uint32_t kOff = (uint32_t)(ks * 16 * 2);
            uint32_t aF[2][4], bH[8][2];
#pragma unroll
            for (int mt = 0; mt < 2; mt++) {
                uint32_t ad = aBase + kOff + (uint32_t)(mt * 16 * AVPAD * 2);
                LDSM4(aF[mt][0], aF[mt][1], aF[mt][2], aF[mt][3], ad);
            }
#pragma unroll
            for (int ntp = 0; ntp < 4; ntp++) {
                uint32_t bd = bBase + kOff + (uint32_t)(ntp * 16 * AVPAD * 2);
                uint32_t r0, r1, r2, r3;
                LDSM4(r0, r1, r2, r3, bd);
                bH[2 * ntp][0] = r0; bH[2 * ntp + 1][0] = r1;
                bH[2 * ntp][1] = r2; bH[2 * ntp + 1][1] = r3;
            }
#pragma unroll
            for (int mt = 0; mt < 2; mt++)
#pragma unroll
                for (int nt = 0; nt < 8; nt++)
                    MMAH(acc[mt][nt], aF[mt], bH[nt]);
        }

        // normalize + attn write (reads e tile back from smem)
        const int k0 = chunk * 64;
#pragma unroll
        for (int i = 0; i < 8; i++) {
            int id = tid + i * 256;
            int row = id >> 3, q = id & 7;
            uint4 ev = *(const uint4*)&sA[row * AVPAD + q * 8];
            const float inv = invs[row];
            const __half2* hp = (const __half2*)&ev;
            float2 f0 = __half22float2(hp[0]);
            float2 f1 = __half22float2(hp[1]);
            float2 f2 = __half22float2(hp[2]);
            float2 f3 = __half22float2(hp[3]);
            float4 v0 = {f0.x * inv, f0.y * inv, f1.x * inv, f1.y * inv};
            float4 v1 = {f2.x * inv, f2.y * inv, f3.x * inv, f3.y * inv};
            size_t ao = (size_t)(rowbase + row) * SS + k0 + q * 8;
            *(float4*)&Az[ao]     = v0;
            *(float4*)&Az[ao + 4] = v1;
        }
        __syncthreads();
    }

#pragma unroll
    for (int mt = 0; mt < 2; mt++) {
#pragma unroll
        for (int nt = 0; nt < 8; nt++) {
            int lrow0 = warpM + mt * 16 + (lane >> 2);
            int col   = nt * 8 + (lane & 3) * 2;
#pragma unroll
            for (int half = 0; half < 2; half++) {
                int lr = lrow0 + half * 8;
                float inv = invs[lr];
                int r = rowbase + lr;
                float vx = acc[mt][nt][half * 2 + 0] * inv;
                float vy = acc[mt][nt][half * 2 + 1] * inv;
                size_t o = ((size_t)b * SS + r) * D_MODEL + h * DEPTH + col;
                __half2 hp = {__float2half(vx), __float2half(vy)};
                *(__half2*)&of[o] = hp;
            }
        }
    }
}

// =====================================================================
extern "C" void kernel_launch(void* const* d_in, const int* in_sizes, int n_in,
                              void* d_out, int out_size)
{
    const float* Q    = (const float*)d_in[0];
    const float* K    = (const float*)d_in[1];
    const float* V    = (const float*)d_in[2];
    const float* mask = (const float*)d_in[3];
    const float* Wq   = (const float*)d_in[4];
    const float* bq   = (const float*)d_in[5];
    const float* Wk   = (const float*)d_in[6];
    const float* bk   = (const float*)d_in[7];
    const float* Wv   = (const float*)d_in[8];
    const float* bv   = (const float*)d_in[9];
    const float* Wo   = (const float*)d_in[10];
    const float* bo   = (const float*)d_in[11];

    float* out = (float*)d_out;

    float *rowsum, *attn;
    __half *inb, *w, *qf, *kf, *vt, *of, *ebuf;
    cudaGetSymbolAddress((void**)&rowsum, g_rowsum);
    cudaGetSymbolAddress((void**)&ebuf, g_e);
    cudaGetSymbolAddress((void**)&inb, g_in);
    cudaGetSymbolAddress((void**)&w, g_w);
    cudaGetSymbolAddress((void**)&qf, g_q_f);
    cudaGetSymbolAddress((void**)&kf, g_k_f);
    cudaGetSymbolAddress((void**)&vt, g_vt);
    cudaGetSymbolAddress((void**)&of, g_o_f);

    if ((size_t)out_size >= OUT_ELEMS + ATTN_ELEMS) {
        attn = out + OUT_ELEMS;
    } else {
        cudaGetSymbolAddress((void**)&attn, g_attn_fallback);
    }

    static bool attr_done = false;
    if (!attr_done) {
        cudaFuncSetAttribute(proj_qkv_kernel, cudaFuncAttributeMaxDynamicSharedMemorySize, 2 * P2STAGE);
        cudaFuncSetAttribute(proj_out_kernel, cudaFuncAttributeMaxDynamicSharedMemorySize, 2 * P2STAGE);
        cudaFuncSetAttribute(scores_mma_kernel, cudaFuncAttributeMaxDynamicSharedMemorySize, 2 * 128 * QPAD * 2);
        cudaFuncSetAttribute(av_mma_kernel, cudaFuncAttributeMaxDynamicSharedMemorySize, AV_SMEM);
        attr_done = true;
    }

    // 1. splits
    dim3 wtBlock(32, 8);
    split_w4_kernel<<<dim3(32, 32, 4), wtBlock>>>(Wq, Wk, Wv, Wo, w);
    split_in3_kernel<<<dim3(NELEM / 256, 3), 256>>>(Q, K, V, inb);

    // 2. QKV projections
    proj_qkv_kernel<<<dim3(8, 32, 3), 256, 2 * P2STAGE>>>(
        inb, w, bq, bk, bv, qf, kf, vt);

    // 3. scores (128x128 tiles) -> e fp16 + rowsum partials
    scores_mma_kernel<<<dim3(16, 16, NZ), 256, 2 * 128 * QPAD * 2>>>(
        qf, kf, mask, ebuf, rowsum);

    // 4. AV (cp.async pipelined, MMA-first) + fused attn normalize; O fp16
    av_mma_kernel<<<dim3(8, NZ), 256, AV_SMEM>>>(ebuf, vt, rowsum, attn, of);

    // 5. output projection (O fp16 x W fp16, 1 MMA, K-chunk 64)
    proj_out_kernel<<<dim3(8, 32), 256, 2 * P2STAGE>>>(
        of, w + (size_t)3 * WELEM, bo, out);
}

// round 16
// speedup vs baseline: 1.1349x; 1.0039x over previous
#include <cuda_runtime.h>
#include <cuda_bf16.h>
#include <cuda_fp16.h>
#include <cstdint>
#include <math.h>

#define D_MODEL   1024
#define NUM_HEADS 16
#define DEPTH     64
#define BB        2
#define SS        2048
#define MROWS     (BB * SS)                              // 4096
#define ATTN_ELEMS ((size_t)BB * NUM_HEADS * SS * SS)    // 134,217,728
#define OUT_ELEMS  ((size_t)MROWS * D_MODEL)             // 4,194,304
#define NZ        (BB * NUM_HEADS)                       // 32
#define RS_W      64
#define NELEM     (MROWS * D_MODEL)                      // 4,194,304
#define WELEM     (D_MODEL * D_MODEL)                    // 1,048,576

// ---------------- scratch (static device globals; no allocations) ------------
__device__ float g_rowsum[(size_t)NZ * SS * RS_W];
__device__ __half g_e[ATTN_ELEMS];                       // unnormalized exp
__device__ __half g_in[3 * (size_t)NELEM];               // QKV inputs fp16
__device__ __half g_w[4 * (size_t)WELEM];                // Wq,Wk,Wv,Wo [n][k] fp16
__device__ __half g_q_f[(size_t)NZ * SS * DEPTH];        // [z,s,d] fp16
__device__ __half g_k_f[(size_t)NZ * SS * DEPTH];        // [z,s,d] fp16
__device__ __half g_vt[(size_t)NZ * SS * DEPTH];         // [z,d,s] fp16 single
__device__ __half g_o_f[(size_t)NELEM];                  // O fp16 single
__device__ float g_attn_fallback[ATTN_ELEMS];

// ============================ PTX helpers ====================================
#define MMAH(d, a, b)                                                         \
    asm volatile("mma.sync.aligned.m16n8k16.row.col.f32.f16.f16.f32 "         \
        "{%0,%1,%2,%3}, {%4,%5,%6,%7}, {%8,%9}, {%0,%1,%2,%3};"               \
        : "+f"((d)[0]), "+f"((d)[1]), "+f"((d)[2]), "+f"((d)[3])              \
        : "r"((a)[0]), "r"((a)[1]), "r"((a)[2]), "r"((a)[3]),                 \
          "r"((b)[0]), "r"((b)[1]))

#define LDSM4(R0, R1, R2, R3, ADDR)                                           \
    asm volatile("ldmatrix.sync.aligned.m8n8.x4.shared.b16 {%0,%1,%2,%3}, [%4];" \
        : "=r"(R0), "=r"(R1), "=r"(R2), "=r"(R3) : "r"(ADDR))

#define CP16(SADDR, GPTR)                                                     \
    asm volatile("cp.async.cg.shared.global [%0], [%1], 16;"                  \
        :: "r"(SADDR), "l"(GPTR))
#define CP_COMMIT() asm volatile("cp.async.commit_group;" ::: "memory")
#define CP_WAIT1()  asm volatile("cp.async.wait_group 1;" ::: "memory")
#define CP_WAIT0()  asm volatile("cp.async.wait_group 0;" ::: "memory")

// streaming (evict-first) stores
#define STG_CS_F4(PTR, V)                                                     \
    asm volatile("st.global.cs.v4.f32 [%0], {%1,%2,%3,%4};"                   \
        :: "l"(PTR), "f"((V).x), "f"((V).y), "f"((V).z), "f"((V).w) : "memory")
#define STG_CS_U4(PTR, V)                                                     \
    asm volatile("st.global.cs.v4.b32 [%0], {%1,%2,%3,%4};"                   \
        :: "l"(PTR), "r"((V).x), "r"((V).y), "r"((V).z), "r"((V).w) : "memory")
// read-only cached vector load
#define LDG_NC_U4(V, PTR)                                                     \
    asm volatile("ld.global.nc.v4.b32 {%0,%1,%2,%3}, [%4];"                   \
        : "=r"((V).x), "=r"((V).y), "=r"((V).z), "=r"((V).w) : "l"(PTR))

__device__ __forceinline__ uint32_t smem_u32(const void* p) {
    uint32_t a;
    asm("{ .reg .u64 t; cvta.to.shared.u64 t, %1; cvt.u32.u64 %0, t; }" : "=r"(a) : "l"(p));
    return a;
}

// ============================ split kernels ==================================
__global__ __launch_bounds__(256)
void split_in3_kernel(const float* __restrict__ Q, const float* __restrict__ K,
                      const float* __restrict__ V, __half* __restrict__ dst)
{
    int z = blockIdx.y;
    const float* A = (z == 0) ? Q : (z == 1) ? K : V;
    size_t i = (size_t)blockIdx.x * 256 + threadIdx.x;
    dst[(size_t)z * NELEM + i] = __float2half(A[i]);
}

__global__ __launch_bounds__(256)
void split_w4_kernel(const float* __restrict__ W0, const float* __restrict__ W1,
                     const float* __restrict__ W2, const float* __restrict__ W3,
                     __half* __restrict__ wt)
{
    __shared__ float t[32][33];
    int z = blockIdx.z;
    const float* W = (z == 0) ? W0 : (z == 1) ? W1 : (z == 2) ? W2 : W3;
    int tx = threadIdx.x, ty = threadIdx.y;
    int n0 = blockIdx.x * 32, k0 = blockIdx.y * 32;
#pragma unroll
    for (int j = 0; j < 4; j++)
        t[ty + j * 8][tx] = W[(size_t)(k0 + ty + j * 8) * D_MODEL + n0 + tx];
    __syncthreads();
#pragma unroll
    for (int j = 0; j < 4; j++) {
        size_t o = (size_t)z * WELEM + (size_t)(n0 + ty + j * 8) * D_MODEL + k0 + tx;
        wt[o] = __float2half(t[tx][ty + j * 8]);
    }
}

// ==================== GEMM core: fp16 x fp16, K-chunk 64, 128x128 ============
#define P2PAD 72
#define P2STAGE 36864     // 2 arrays * 128*72*2
#define P2_OFF_A 0
#define P2_OFF_B 18432

template <int MODE>
__device__ __forceinline__ void gemm_fp16_core(
    const __half* __restrict__ a, const __half* __restrict__ wh,
    const float* __restrict__ bias, char* smem,
    int blockRow, int blockCol,
    __half* __restrict__ out_h, float* __restrict__ out_f)
{
    const uint32_t sb0 = smem_u32(smem);
    const int tid  = threadIdx.x;
    const int lane = tid & 31;
    const int wid  = tid >> 5;
    const int warpM = (wid >> 2) * 64;
    const int warpN = (wid & 3) * 32;
    const int lmRow = lane & 15;
    const int lmK   = (lane >> 4) * 8;

    float acc[4][4][4];
#pragma unroll
    for (int mt = 0; mt < 4; mt++)
#pragma unroll
        for (int nt = 0; nt < 4; nt++)
#pragma unroll
            for (int r = 0; r < 4; r++) acc[mt][nt][r] = 0.0f;

    auto load_stage = [&](int stage, int chunk) {
        const int k0 = chunk * 64;
        const uint32_t sb = sb0 + stage * P2STAGE;
#pragma unroll
        for (int j = 0; j < 4; j++) {
            int id = tid + j * 256;
            int row = id >> 3, q = id & 7;
            uint32_t so = (uint32_t)(row * 144 + q * 16);
            CP16(sb + P2_OFF_A + so, &a[(size_t)(blockRow + row) * D_MODEL + k0 + q * 8]);
            CP16(sb + P2_OFF_B + so, &wh[(size_t)(blockCol + row) * D_MODEL + k0 + q * 8]);
        }
        CP_COMMIT();
    };

    load_stage(0, 0);

    for (int chunk = 0; chunk < 16; chunk++) {
        if (chunk < 15) { load_stage((chunk + 1) & 1, chunk + 1); CP_WAIT1(); }
        else           { CP_WAIT0(); }
        __syncthreads();

        const uint32_t sb = sb0 + (chunk & 1) * P2STAGE;
        const uint32_t aBase = sb + P2_OFF_A + (uint32_t)(((warpM + lmRow) * P2PAD + lmK) * 2);
        const uint32_t bBase = sb + P2_OFF_B + (uint32_t)(((warpN + lmRow) * P2PAD + lmK) * 2);

#pragma unroll
        for (int ks = 0; ks < 4; ks++) {
            const uint32_t kOff = (uint32_t)(ks * 16 * 2);
            uint32_t aF[4][4], bH[4][2];
#pragma unroll
            for (int mt = 0; mt < 4; mt++) {
                uint32_t ad = aBase + kOff + (uint32_t)(mt * 16 * P2PAD * 2);
                LDSM4(aF[mt][0], aF[mt][1], aF[mt][2], aF[mt][3], ad);
            }
#pragma unroll
            for (int ntp = 0; ntp < 2; ntp++) {
                uint32_t bd = bBase + kOff + (uint32_t)(ntp * 16 * P2PAD * 2);
                uint32_t r0, r1, r2, r3;
                LDSM4(r0, r1, r2, r3, bd);
                bH[2 * ntp][0] = r0; bH[2 * ntp + 1][0] = r1;
                bH[2 * ntp][1] = r2; bH[2 * ntp + 1][1] = r3;
            }
#pragma unroll
            for (int mt = 0; mt < 4; mt++)
#pragma unroll
                for (int nt = 0; nt < 4; nt++)
                    MMAH(acc[mt][nt], aF[mt], bH[nt]);
        }
        __syncthreads();
    }

#pragma unroll
    for (int mt = 0; mt < 4; mt++) {
#pragma unroll
        for (int nt = 0; nt < 4; nt++) {
            int row0 = blockRow + warpM + mt * 16 + (lane >> 2);
            int col  = blockCol + warpN + nt * 8 + (lane & 3) * 2;
            float b0 = bias[col], b1 = bias[col + 1];
#pragma unroll
            for (int half = 0; half < 2; half++) {
                int r = row0 + half * 8;
                float vx = acc[mt][nt][half * 2 + 0] + b0;
                float vy = acc[mt][nt][half * 2 + 1] + b1;
                if (MODE == 3) {
                    float2 v = {vx, vy};
                    *(float2*)&out_f[(size_t)r * D_MODEL + col] = v;
                } else {
                    int z = (r >> 11) * NUM_HEADS + (col >> 6);
                    int s = r & (SS - 1);
                    int d = col & (DEPTH - 1);
                    if (MODE == 0 || MODE == 1) {
                        size_t o = ((size_t)z * SS + s) * DEPTH + d;
                        __half2 hp = {__float2half(vx), __float2half(vy)};
                        *(__half2*)&out_h[o] = hp;
                    } else {
                        size_t o = ((size_t)z * DEPTH + d) * SS + s;
                        out_h[o]      = __float2half(vx);
                        out_h[o + SS] = __float2half(vy);
                    }
                }
            }
        }
    }
}

__global__ __launch_bounds__(256, 2)
void proj_qkv_kernel(const __half* __restrict__ in, const __half* __restrict__ w,
                     const float* __restrict__ bq, const float* __restrict__ bk,
                     const float* __restrict__ bv,
                     __half* __restrict__ qf, __half* __restrict__ kf,
                     __half* __restrict__ vt)
{
    extern __shared__ char smem[];
    const int zz = blockIdx.z;
    const __half* a  = in + (size_t)zz * NELEM;
    const __half* wh = w + (size_t)zz * WELEM;
    if (zz == 0)
        gemm_fp16_core<0>(a, wh, bq, smem, blockIdx.y * 128, blockIdx.x * 128, qf, nullptr);
    else if (zz == 1)
        gemm_fp16_core<1>(a, wh, bk, smem, blockIdx.y * 128, blockIdx.x * 128, kf, nullptr);
    else
        gemm_fp16_core<2>(a, wh, bv, smem, blockIdx.y * 128, blockIdx.x * 128, vt, nullptr);
}

__global__ __launch_bounds__(256, 2)
void proj_out_kernel(const __half* __restrict__ of, const __half* __restrict__ w,
                     const float* __restrict__ bias, float* __restrict__ C)
{
    extern __shared__ char smem[];
    gemm_fp16_core<3>(of, w, bias, smem, blockIdx.y * 128, blockIdx.x * 128, nullptr, C);
}

// ==================== scores: single-fp16 mma -> e fp16 (staged, .cs) ========
#define QPAD 72
#define EPAD 136

__global__ __launch_bounds__(256, 2)
void scores_mma_kernel(const __half* __restrict__ qf, const __half* __restrict__ kf,
                       const float* __restrict__ mask, __half* __restrict__ eout,
                       float* __restrict__ rowsum)
{
    extern __shared__ char sm[];
    const uint32_t sq = smem_u32(sm);
    __half* sQh = (__half*)sm;
    __half* sKh = sQh + 128 * QPAD;
    const uint32_t OQH = 0, OKH = 128 * QPAD * 2;

    const int z = blockIdx.z;
    const int b = z / NUM_HEADS;
    const int tid = threadIdx.x, lane = tid & 31, wid = tid >> 5;
    const int warpM = (wid >> 2) * 64, warpN = (wid & 3) * 32;
    const int blockRow = blockIdx.y * 128, blockCol = blockIdx.x * 128;
    const int lmRow = lane & 15, lmK = (lane >> 4) * 8;

#pragma unroll
    for (int i = 0; i < 4; i++) {
        int id = tid + i * 256;
        int row = id >> 3, q = id & 7;
        uint4 vq, vk;
        LDG_NC_U4(vq, (const uint4*)&qf[((size_t)z * SS + blockRow + row) * DEPTH + q * 8]);
        LDG_NC_U4(vk, (const uint4*)&kf[((size_t)z * SS + blockCol + row) * DEPTH + q * 8]);
        int so = row * QPAD + q * 8;
        *(uint4*)&sQh[so] = vq;
        *(uint4*)&sKh[so] = vk;
    }
    __syncthreads();

    float acc[4][4][4];
#pragma unroll
    for (int mt = 0; mt < 4; mt++)
#pragma unroll
        for (int nt = 0; nt < 4; nt++)
#pragma unroll
            for (int r = 0; r < 4; r++) acc[mt][nt][r] = 0.0f;

    const uint32_t aAddrBase = sq + (uint32_t)(((warpM + lmRow) * QPAD + lmK) * 2);
    const uint32_t bAddrBase = sq + (uint32_t)(((warpN + lmRow) * QPAD + lmK) * 2);

#pragma unroll
    for (int ks = 0; ks < 4; ks++) {
        const uint32_t kOff = (uint32_t)(ks * 16 * 2);
        uint32_t aH[4][4], bH[4][2];
#pragma unroll
        for (int mt = 0; mt < 4; mt++) {
            uint32_t ad = aAddrBase + kOff + (uint32_t)(mt * 16 * QPAD * 2);
            LDSM4(aH[mt][0], aH[mt][1], aH[mt][2], aH[mt][3], ad + OQH);
        }
#pragma unroll
        for (int ntp = 0; ntp < 2; ntp++) {
            uint32_t bd = bAddrBase + kOff + (uint32_t)(ntp * 16 * QPAD * 2);
            uint32_t r0, r1, r2, r3;
            LDSM4(r0, r1, r2, r3, bd + OKH);
            bH[2 * ntp][0] = r0; bH[2 * ntp + 1][0] = r1;
            bH[2 * ntp][1] = r2; bH[2 * ntp + 1][1] = r3;
        }
#pragma unroll
        for (int mt = 0; mt < 4; mt++)
#pragma unroll
            for (int nt = 0; nt < 4; nt++)
                MMAH(acc[mt][nt], aH[mt], bH[nt]);
    }

    float mcol[4][2];
#pragma unroll
    for (int nt = 0; nt < 4; nt++) {
        int col = blockCol + warpN + nt * 8 + (lane & 3) * 2;
        mcol[nt][0] = mask[(size_t)b * SS + col]     * (-1e9f);
        mcol[nt][1] = mask[(size_t)b * SS + col + 1] * (-1e9f);
    }

    __syncthreads();
    __half* sE = (__half*)sm;

#pragma unroll
    for (int mt = 0; mt < 4; mt++) {
#pragma unroll
        for (int half = 0; half < 2; half++) {
            int lrow = warpM + mt * 16 + (lane >> 2) + half * 8;
            float rs = 0.0f;
#pragma unroll
            for (int nt = 0; nt < 4; nt++) {
                int lcol = warpN + nt * 8 + (lane & 3) * 2;
                float e0 = __expf(acc[mt][nt][half * 2 + 0] * 0.125f + mcol[nt][0]);
                float e1 = __expf(acc[mt][nt][half * 2 + 1] * 0.125f + mcol[nt][1]);
                rs += e0 + e1;
                *(__half2*)&sE[lrow * EPAD + lcol] = __floats2half2_rn(e0, e1);
            }
            rs += __shfl_xor_sync(0xffffffffu, rs, 1);
            rs += __shfl_xor_sync(0xffffffffu, rs, 2);
            if ((lane & 3) == 0)
                rowsum[((size_t)z * SS + blockRow + lrow) * RS_W + blockIdx.x * 4 + (wid & 3)] = rs;
        }
    }
    __syncthreads();

    __half* Ez = eout + (size_t)z * SS * SS;
#pragma unroll
    for (int i = 0; i < 8; i++) {
        int id = tid + i * 256;
        int row = id >> 4, q = id & 15;
        uint4 v = *(const uint4*)&sE[row * EPAD + q * 8];
        STG_CS_U4(&Ez[(size_t)(blockRow + row) * SS + blockCol + q * 8], v);
    }
}

// ==================== AV: cp.async pipelined, .cs attn stores ================
#define AVPAD 72
#define AV_STAGE   46080      // A 256*72*2 + B 64*72*2
#define AV_OFF_B   36864
#define AV_OFF_INV 92160      // after 2 stages
#define AV_SMEM    93184      // + 256*4

__global__ __launch_bounds__(256, 2)
void av_mma_kernel(const __half* __restrict__ e, const __half* __restrict__ vt,
                   const float* __restrict__ rowsum, float* __restrict__ attn,
                   __half* __restrict__ of)
{
    extern __shared__ char avsm[];
    const uint32_t sb0 = smem_u32(avsm);
    float* invs = (float*)(avsm + AV_OFF_INV);

    const int z = blockIdx.y;
    const int b = z / NUM_HEADS, h = z % NUM_HEADS;
    const int rowbase = blockIdx.x * 256;
    const int tid = threadIdx.x, lane = tid & 31, wid = tid >> 5;
    const int warpM = wid * 32;
    const int lmRow = lane & 15, lmK = (lane >> 4) * 8;

    {
        const float* rp = &rowsum[((size_t)z * SS + rowbase + tid) * RS_W];
        float s = 0.0f;
#pragma unroll
        for (int j = 0; j < RS_W; j++) s += rp[j];
        invs[tid] = 1.0f / s;
    }
    __syncthreads();

    const __half* Ez = e + (size_t)z * SS * SS;
    float* Az = attn + (size_t)z * SS * SS;

    auto load_stage = [&](int stage, int chunk) {
        const int k0 = chunk * 64;
        const uint32_t sb = sb0 + stage * AV_STAGE;
#pragma unroll
        for (int i = 0; i < 8; i++) {
            int id = tid + i * 256;
            int row = id >> 3, q = id & 7;
            CP16(sb + (uint32_t)(row * 144 + q * 16),
                 &Ez[(size_t)(rowbase + row) * SS + k0 + q * 8]);
        }
#pragma unroll
        for (int i = 0; i < 2; i++) {
            int id = tid + i * 256;
            int row = id >> 3, q = id & 7;
            CP16(sb + AV_OFF_B + (uint32_t)(row * 144 + q * 16),
                 &vt[((size_t)z * DEPTH + row) * SS + k0 + q * 8]);
        }
        CP_COMMIT();
    };

    float acc[2][8][4];
#pragma unroll
    for (int mt = 0; mt < 2; mt++)
#pragma unroll
        for (int nt = 0; nt < 8; nt++)
#pragma unroll
            for (int r = 0; r < 4; r++) acc[mt][nt][r] = 0.0f;

    load_stage(0, 0);

    for (int chunk = 0; chunk < 32; chunk++) {
        if (chunk < 31) { load_stage((chunk + 1) & 1, chunk + 1); CP_WAIT1(); }
        else           { CP_WAIT0(); }
        __syncthreads();

        const uint32_t sb = sb0 + (chunk & 1) * AV_STAGE;
        const __half* sA = (const __half*)(avsm + (chunk & 1) * AV_STAGE);
        const uint32_t aBase = sb + (uint32_t)(((warpM + lmRow) * AVPAD + lmK) * 2);
        const uint32_t bBase = sb + AV_OFF_B + (uint32_t)((lmRow * AVPAD + lmK) * 2);

        // MMA first (tensor pipe starts immediately)
#pragma unroll
        for (int ks = 0; ks < 4; ks++) {
            const uint32_t kOff = (uint32_t)(ks * 16 * 2);
            uint32_t aF[2][4], bH[8][2];
#pragma unroll
            for (int mt = 0; mt < 2; mt++) {
                uint32_t ad = aBase + kOff + (uint32_t)(mt * 16 * AVPAD * 2);
                LDSM4(aF[mt][0], aF[mt][1], aF[mt][2], aF[mt][3], ad);
            }
#pragma unroll
            for (int ntp = 0; ntp < 4; ntp++) {
                uint32_t bd = bBase + kOff + (uint32_t)(ntp * 16 * AVPAD * 2);
                uint32_t r0, r1, r2, r3;
                LDSM4(r0, r1, r2, r3, bd);
                bH[2 * ntp][0] = r0; bH[2 * ntp + 1][0] = r1;
                bH[2 * ntp][1] = r2; bH[2 * ntp + 1][1] = r3;
            }
#pragma unroll
            for (int mt = 0; mt < 2; mt++)
#pragma unroll
                for (int nt = 0; nt < 8; nt++)
                    MMAH(acc[mt][nt], aF[mt], bH[nt]);
        }

        // normalize + attn write (streaming .cs stores)
        const int k0 = chunk * 64;
#pragma unroll
        for (int i = 0; i < 8; i++) {
            int id = tid + i * 256;
            int row = id >> 3, q = id & 7;
            uint4 ev = *(const uint4*)&sA[row * AVPAD + q * 8];
            const float inv = invs[row];
            const __half2* hp = (const __half2*)&ev;
            float2 f0 = __half22float2(hp[0]);
            float2 f1 = __half22float2(hp[1]);
            float2 f2 = __half22float2(hp[2]);
            float2 f3 = __half22float2(hp[3]);
            float4 v0 = {f0.x * inv, f0.y * inv, f1.x * inv, f1.y * inv};
            float4 v1 = {f2.x * inv, f2.y * inv, f3.x * inv, f3.y * inv};
            size_t ao = (size_t)(rowbase + row) * SS + k0 + q * 8;
            STG_CS_F4(&Az[ao],     v0);
            STG_CS_F4(&Az[ao + 4], v1);
        }
        __syncthreads();
    }

#pragma unroll
    for (int mt = 0; mt < 2; mt++) {
#pragma unroll
        for (int nt = 0; nt < 8; nt++) {
            int lrow0 = warpM + mt * 16 + (lane >> 2);
            int col   = nt * 8 + (lane & 3) * 2;
#pragma unroll
            for (int half = 0; half < 2; half++) {
                int lr = lrow0 + half * 8;
                float inv = invs[lr];
                int r = rowbase + lr;
                float vx = acc[mt][nt][half * 2 + 0] * inv;
                float vy = acc[mt][nt][half * 2 + 1] * inv;
                size_t o = ((size_t)b * SS + r) * D_MODEL + h * DEPTH + col;
                __half2 hp = {__float2half(vx), __float2half(vy)};
                *(__half2*)&of[o] = hp;
            }
        }
    }
}

// =====================================================================
extern "C" void kernel_launch(void* const* d_in, const int* in_sizes, int n_in,
                              void* d_out, int out_size)
{
    const float* Q    = (const float*)d_in[0];
    const float* K    = (const float*)d_in[1];
    const float* V    = (const float*)d_in[2];
    const float* mask = (const float*)d_in[3];
    const float* Wq   = (const float*)d_in[4];
    const float* bq   = (const float*)d_in[5];
    const float* Wk   = (const float*)d_in[6];
    const float* bk   = (const float*)d_in[7];
    const float* Wv   = (const float*)d_in[8];
    const float* bv   = (const float*)d_in[9];
    const float* Wo   = (const float*)d_in[10];
    const float* bo   = (const float*)d_in[11];

    float* out = (float*)d_out;

    float *rowsum, *attn;
    __half *inb, *w, *qf, *kf, *vt, *of, *ebuf;
    cudaGetSymbolAddress((void**)&rowsum, g_rowsum);
    cudaGetSymbolAddress((void**)&ebuf, g_e);
    cudaGetSymbolAddress((void**)&inb, g_in);
    cudaGetSymbolAddress((void**)&w, g_w);
    cudaGetSymbolAddress((void**)&qf, g_q_f);
    cudaGetSymbolAddress((void**)&kf, g_k_f);
    cudaGetSymbolAddress((void**)&vt, g_vt);
    cudaGetSymbolAddress((void**)&of, g_o_f);

    if ((size_t)out_size >= OUT_ELEMS + ATTN_ELEMS) {
        attn = out + OUT_ELEMS;
    } else {
        cudaGetSymbolAddress((void**)&attn, g_attn_fallback);
    }

    static bool attr_done = false;
    if (!attr_done) {
        cudaFuncSetAttribute(proj_qkv_kernel, cudaFuncAttributeMaxDynamicSharedMemorySize, 2 * P2STAGE);
        cudaFuncSetAttribute(proj_out_kernel, cudaFuncAttributeMaxDynamicSharedMemorySize, 2 * P2STAGE);
        cudaFuncSetAttribute(scores_mma_kernel, cudaFuncAttributeMaxDynamicSharedMemorySize, 2 * 128 * QPAD * 2);
        cudaFuncSetAttribute(av_mma_kernel, cudaFuncAttributeMaxDynamicSharedMemorySize, AV_SMEM);
        attr_done = true;
    }

    // 1. splits
    dim3 wtBlock(32, 8);
    split_w4_kernel<<<dim3(32, 32, 4), wtBlock>>>(Wq, Wk, Wv, Wo, w);
    split_in3_kernel<<<dim3(NELEM / 256, 3), 256>>>(Q, K, V, inb);

    // 2. QKV projections
    proj_qkv_kernel<<<dim3(8, 32, 3), 256, 2 * P2STAGE>>>(
        inb, w, bq, bk, bv, qf, kf, vt);

    // 3. scores -> e fp16 (.cs) + rowsum partials
    scores_mma_kernel<<<dim3(16, 16, NZ), 256, 2 * 128 * QPAD * 2>>>(
        qf, kf, mask, ebuf, rowsum);

    // 4. AV (cp.async pipelined) + fused attn normalize (.cs stores)
    av_mma_kernel<<<dim3(8, NZ), 256, AV_SMEM>>>(ebuf, vt, rowsum, attn, of);

    // 5. output projection
    proj_out_kernel<<<dim3(8, 32), 256, 2 * P2STAGE>>>(
        of, w + (size_t)3 * WELEM, bo, out);
}

// round 17
// speedup vs baseline: 1.2197x; 1.0748x over previous
#include <cuda_runtime.h>
#include <cuda_bf16.h>
#include <cuda_fp16.h>
#include <cstdint>
#include <math.h>

#define D_MODEL   1024
#define NUM_HEADS 16
#define DEPTH     64
#define BB        2
#define SS        2048
#define MROWS     (BB * SS)                              // 4096
#define ATTN_ELEMS ((size_t)BB * NUM_HEADS * SS * SS)    // 134,217,728
#define OUT_ELEMS  ((size_t)MROWS * D_MODEL)             // 4,194,304
#define NZ        (BB * NUM_HEADS)                       // 32
#define RS_W      64
#define NELEM     (MROWS * D_MODEL)                      // 4,194,304
#define WELEM     (D_MODEL * D_MODEL)                    // 1,048,576

// exp(x) = 2^(x*log2e): fold 0.125*log2e and -1e9*log2e into the FFMA
#define SCALE_L2E 0.18033688011112042f
#define MASK_L2E  (-1.4426950408889634e9f)

// ---------------- scratch (static device globals; no allocations) ------------
__device__ float g_rowsum[(size_t)NZ * SS * RS_W];
__device__ __half g_e[ATTN_ELEMS];                       // unnormalized exp
__device__ __half g_in[3 * (size_t)NELEM];               // QKV inputs fp16
__device__ __half g_w[4 * (size_t)WELEM];                // Wq,Wk,Wv,Wo [n][k] fp16
__device__ __half g_q_f[(size_t)NZ * SS * DEPTH];        // [z,s,d] fp16
__device__ __half g_k_f[(size_t)NZ * SS * DEPTH];        // [z,s,d] fp16
__device__ __half g_vt[(size_t)NZ * SS * DEPTH];         // [z,d,s] fp16 single
__device__ __half g_o_f[(size_t)NELEM];                  // O fp16 single
__device__ float g_attn_fallback[ATTN_ELEMS];

// ============================ PTX helpers ====================================
#define MMAH(d, a, b)                                                         \
    asm volatile("mma.sync.aligned.m16n8k16.row.col.f32.f16.f16.f32 "         \
        "{%0,%1,%2,%3}, {%4,%5,%6,%7}, {%8,%9}, {%0,%1,%2,%3};"               \
        : "+f"((d)[0]), "+f"((d)[1]), "+f"((d)[2]), "+f"((d)[3])              \
        : "r"((a)[0]), "r"((a)[1]), "r"((a)[2]), "r"((a)[3]),                 \
          "r"((b)[0]), "r"((b)[1]))

#define LDSM4(R0, R1, R2, R3, ADDR)                                           \
    asm volatile("ldmatrix.sync.aligned.m8n8.x4.shared.b16 {%0,%1,%2,%3}, [%4];" \
        : "=r"(R0), "=r"(R1), "=r"(R2), "=r"(R3) : "r"(ADDR))

#define CP16(SADDR, GPTR)                                                     \
    asm volatile("cp.async.cg.shared.global [%0], [%1], 16;"                  \
        :: "r"(SADDR), "l"(GPTR))
#define CP_COMMIT() asm volatile("cp.async.commit_group;" ::: "memory")
#define CP_WAIT1()  asm volatile("cp.async.wait_group 1;" ::: "memory")
#define CP_WAIT0()  asm volatile("cp.async.wait_group 0;" ::: "memory")

#define STG_CS_F4(PTR, V)                                                     \
    asm volatile("st.global.cs.v4.f32 [%0], {%1,%2,%3,%4};"                   \
        :: "l"(PTR), "f"((V).x), "f"((V).y), "f"((V).z), "f"((V).w) : "memory")
#define STG_CS_U4(PTR, V)                                                     \
    asm volatile("st.global.cs.v4.b32 [%0], {%1,%2,%3,%4};"                   \
        :: "l"(PTR), "r"((V).x), "r"((V).y), "r"((V).z), "r"((V).w) : "memory")

#define EX2F(D, X) asm("ex2.approx.f32 %0, %1;" : "=f"(D) : "f"(X))

__device__ __forceinline__ uint32_t smem_u32(const void* p) {
    uint32_t a;
    asm("{ .reg .u64 t; cvta.to.shared.u64 t, %1; cvt.u32.u64 %0, t; }" : "=r"(a) : "l"(p));
    return a;
}

// ============================ split kernels ==================================
__global__ __launch_bounds__(256)
void split_in3_kernel(const float* __restrict__ Q, const float* __restrict__ K,
                      const float* __restrict__ V, __half* __restrict__ dst)
{
    int z = blockIdx.y;
    const float* A = (z == 0) ? Q : (z == 1) ? K : V;
    size_t i4 = (size_t)blockIdx.x * 256 + threadIdx.x;
    float4 x = ((const float4*)A)[i4];
    __half2 h0 = __floats2half2_rn(x.x, x.y);
    __half2 h1 = __floats2half2_rn(x.z, x.w);
    uint2 v = {*(uint32_t*)&h0, *(uint32_t*)&h1};
    *(uint2*)&dst[(size_t)z * NELEM + i4 * 4] = v;
}

__global__ __launch_bounds__(256)
void split_w4_kernel(const float* __restrict__ W0, const float* __restrict__ W1,
                     const float* __restrict__ W2, const float* __restrict__ W3,
                     __half* __restrict__ wt)
{
    __shared__ float t[32][33];
    int z = blockIdx.z;
    const float* W = (z == 0) ? W0 : (z == 1) ? W1 : (z == 2) ? W2 : W3;
    int tx = threadIdx.x, ty = threadIdx.y;
    int n0 = blockIdx.x * 32, k0 = blockIdx.y * 32;
#pragma unroll
    for (int j = 0; j < 4; j++)
        t[ty + j * 8][tx] = W[(size_t)(k0 + ty + j * 8) * D_MODEL + n0 + tx];
    __syncthreads();
#pragma unroll
    for (int j = 0; j < 4; j++) {
        size_t o = (size_t)z * WELEM + (size_t)(n0 + ty + j * 8) * D_MODEL + k0 + tx;
        wt[o] = __float2half(t[tx][ty + j * 8]);
    }
}

// ==================== GEMM core: fp16 x fp16, K-chunk 64, 128x128 ============
#define P2PAD 72
#define P2STAGE 36864     // 2 arrays * 128*72*2
#define P2_OFF_A 0
#define P2_OFF_B 18432

template <int MODE>
__device__ __forceinline__ void gemm_fp16_core(
    const __half* __restrict__ a, const __half* __restrict__ wh,
    const float* __restrict__ bias, char* smem,
    int blockRow, int blockCol,
    __half* __restrict__ out_h, float* __restrict__ out_f)
{
    const uint32_t sb0 = smem_u32(smem);
    const int tid  = threadIdx.x;
    const int lane = tid & 31;
    const int wid  = tid >> 5;
    const int warpM = (wid >> 2) * 64;
    const int warpN = (wid & 3) * 32;
    const int lmRow = lane & 15;
    const int lmK   = (lane >> 4) * 8;

    float acc[4][4][4];
#pragma unroll
    for (int mt = 0; mt < 4; mt++)
#pragma unroll
        for (int nt = 0; nt < 4; nt++)
#pragma unroll
            for (int r = 0; r < 4; r++) acc[mt][nt][r] = 0.0f;

    auto load_stage = [&](int stage, int chunk) {
        const int k0 = chunk * 64;
        const uint32_t sb = sb0 + stage * P2STAGE;
#pragma unroll
        for (int j = 0; j < 4; j++) {
            int id = tid + j * 256;
            int row = id >> 3, q = id & 7;
            uint32_t so = (uint32_t)(row * 144 + q * 16);
            CP16(sb + P2_OFF_A + so, &a[(size_t)(blockRow + row) * D_MODEL + k0 + q * 8]);
            CP16(sb + P2_OFF_B + so, &wh[(size_t)(blockCol + row) * D_MODEL + k0 + q * 8]);
        }
        CP_COMMIT();
    };

    load_stage(0, 0);

    for (int chunk = 0; chunk < 16; chunk++) {
        if (chunk < 15) { load_stage((chunk + 1) & 1, chunk + 1); CP_WAIT1(); }
        else           { CP_WAIT0(); }
        __syncthreads();

        const uint32_t sb = sb0 + (chunk & 1) * P2STAGE;
        const uint32_t aBase = sb + P2_OFF_A + (uint32_t)(((warpM + lmRow) * P2PAD + lmK) * 2);
        const uint32_t bBase = sb + P2_OFF_B + (uint32_t)(((warpN + lmRow) * P2PAD + lmK) * 2);

#pragma unroll
        for (int ks = 0; ks < 4; ks++) {
            const uint32_t kOff = (uint32_t)(ks * 16 * 2);
            uint32_t aF[4][4], bH[4][2];
#pragma unroll
            for (int mt = 0; mt < 4; mt++) {
                uint32_t ad = aBase + kOff + (uint32_t)(mt * 16 * P2PAD * 2);
                LDSM4(aF[mt][0], aF[mt][1], aF[mt][2], aF[mt][3], ad);
            }
#pragma unroll
            for (int ntp = 0; ntp < 2; ntp++) {
                uint32_t bd = bBase + kOff + (uint32_t)(ntp * 16 * P2PAD * 2);
                uint32_t r0, r1, r2, r3;
                LDSM4(r0, r1, r2, r3, bd);
                bH[2 * ntp][0] = r0; bH[2 * ntp + 1][0] = r1;
                bH[2 * ntp][1] = r2; bH[2 * ntp + 1][1] = r3;
            }
#pragma unroll
            for (int mt = 0; mt < 4; mt++)
#pragma unroll
                for (int nt = 0; nt < 4; nt++)
                    MMAH(acc[mt][nt], aF[mt], bH[nt]);
        }
        __syncthreads();
    }

#pragma unroll
    for (int mt = 0; mt < 4; mt++) {
#pragma unroll
        for (int nt = 0; nt < 4; nt++) {
            int row0 = blockRow + warpM + mt * 16 + (lane >> 2);
            int col  = blockCol + warpN + nt * 8 + (lane & 3) * 2;
            float b0 = bias[col], b1 = bias[col + 1];
#pragma unroll
            for (int half = 0; half < 2; half++) {
                int r = row0 + half * 8;
                float vx = acc[mt][nt][half * 2 + 0] + b0;
                float vy = acc[mt][nt][half * 2 + 1] + b1;
                if (MODE == 3) {
                    float2 v = {vx, vy};
                    *(float2*)&out_f[(size_t)r * D_MODEL + col] = v;
                } else {
                    int z = (r >> 11) * NUM_HEADS + (col >> 6);
                    int s = r & (SS - 1);
                    int d = col & (DEPTH - 1);
                    if (MODE == 0 || MODE == 1) {
                        size_t o = ((size_t)z * SS + s) * DEPTH + d;
                        __half2 hp = {__float2half(vx), __float2half(vy)};
                        *(__half2*)&out_h[o] = hp;
                    } else {
                        size_t o = ((size_t)z * DEPTH + d) * SS + s;
                        out_h[o]      = __float2half(vx);
                        out_h[o + SS] = __float2half(vy);
                    }
                }
            }
        }
    }
}

__global__ __launch_bounds__(256, 2)
void proj_qkv_kernel(const __half* __restrict__ in, const __half* __restrict__ w,
                     const float* __restrict__ bq, const float* __restrict__ bk,
                     const float* __restrict__ bv,
                     __half* __restrict__ qf, __half* __restrict__ kf,
                     __half* __restrict__ vt)
{
    extern __shared__ char smem[];
    const int zz = blockIdx.z;
    const __half* a  = in + (size_t)zz * NELEM;
    const __half* wh = w + (size_t)zz * WELEM;
    if (zz == 0)
        gemm_fp16_core<0>(a, wh, bq, smem, blockIdx.y * 128, blockIdx.x * 128, qf, nullptr);
    else if (zz == 1)
        gemm_fp16_core<1>(a, wh, bk, smem, blockIdx.y * 128, blockIdx.x * 128, kf, nullptr);
    else
        gemm_fp16_core<2>(a, wh, bv, smem, blockIdx.y * 128, blockIdx.x * 128, vt, nullptr);
}

__global__ __launch_bounds__(256, 2)
void proj_out_kernel(const __half* __restrict__ of, const __half* __restrict__ w,
                     const float* __restrict__ bias, float* __restrict__ C)
{
    extern __shared__ char smem[];
    gemm_fp16_core<3>(of, w, bias, smem, blockIdx.y * 128, blockIdx.x * 128, nullptr, C);
}

// ==================== scores: single-fp16 mma -> e fp16 (staged, .cs) ========
#define QPAD 72
#define EPAD 136

__global__ __launch_bounds__(256, 2)
void scores_mma_kernel(const __half* __restrict__ qf, const __half* __restrict__ kf,
                       const float* __restrict__ mask, __half* __restrict__ eout,
                       float* __restrict__ rowsum)
{
    extern __shared__ char sm[];
    const uint32_t sq = smem_u32(sm);
    const uint32_t OQH = 0, OKH = 128 * QPAD * 2;

    const int z = blockIdx.z;
    const int b = z / NUM_HEADS;
    const int tid = threadIdx.x, lane = tid & 31, wid = tid >> 5;
    const int warpM = (wid >> 2) * 64, warpN = (wid & 3) * 32;
    const int blockRow = blockIdx.y * 128, blockCol = blockIdx.x * 128;
    const int lmRow = lane & 15, lmK = (lane >> 4) * 8;

    // operand loads via cp.async (no register staging)
#pragma unroll
    for (int i = 0; i < 4; i++) {
        int id = tid + i * 256;
        int row = id >> 3, q = id & 7;
        uint32_t so = (uint32_t)(row * 144 + q * 16);
        CP16(sq + OQH + so, &qf[((size_t)z * SS + blockRow + row) * DEPTH + q * 8]);
        CP16(sq + OKH + so, &kf[((size_t)z * SS + blockCol + row) * DEPTH + q * 8]);
    }
    CP_COMMIT();
    CP_WAIT0();
    __syncthreads();

    float acc[4][4][4];
#pragma unroll
    for (int mt = 0; mt < 4; mt++)
#pragma unroll
        for (int nt = 0; nt < 4; nt++)
#pragma unroll
            for (int r = 0; r < 4; r++) acc[mt][nt][r] = 0.0f;

    const uint32_t aAddrBase = sq + (uint32_t)(((warpM + lmRow) * QPAD + lmK) * 2);
    const uint32_t bAddrBase = sq + (uint32_t)(((warpN + lmRow) * QPAD + lmK) * 2);

#pragma unroll
    for (int ks = 0; ks < 4; ks++) {
        const uint32_t kOff = (uint32_t)(ks * 16 * 2);
        uint32_t aH[4][4], bH[4][2];
#pragma unroll
        for (int mt = 0; mt < 4; mt++) {
            uint32_t ad = aAddrBase + kOff + (uint32_t)(mt * 16 * QPAD * 2);
            LDSM4(aH[mt][0], aH[mt][1], aH[mt][2], aH[mt][3], ad + OQH);
        }
#pragma unroll
        for (int ntp = 0; ntp < 2; ntp++) {
            uint32_t bd = bAddrBase + kOff + (uint32_t)(ntp * 16 * QPAD * 2);
            uint32_t r0, r1, r2, r3;
            LDSM4(r0, r1, r2, r3, bd + OKH);
            bH[2 * ntp][0] = r0; bH[2 * ntp + 1][0] = r1;
            bH[2 * ntp][1] = r2; bH[2 * ntp + 1][1] = r3;
        }
#pragma unroll
        for (int mt = 0; mt < 4; mt++)
#pragma unroll
            for (int nt = 0; nt < 4; nt++)
                MMAH(acc[mt][nt], aH[mt], bH[nt]);
    }

    float mcol[4][2];
#pragma unroll
    for (int nt = 0; nt < 4; nt++) {
        int col = blockCol + warpN + nt * 8 + (lane & 3) * 2;
        mcol[nt][0] = mask[(size_t)b * SS + col]     * MASK_L2E;
        mcol[nt][1] = mask[(size_t)b * SS + col + 1] * MASK_L2E;
    }

    __syncthreads();
    __half* sE = (__half*)sm;

#pragma unroll
    for (int mt = 0; mt < 4; mt++) {
#pragma unroll
        for (int half = 0; half < 2; half++) {
            int lrow = warpM + mt * 16 + (lane >> 2) + half * 8;
            float rs = 0.0f;
#pragma unroll
            for (int nt = 0; nt < 4; nt++) {
                int lcol = warpN + nt * 8 + (lane & 3) * 2;
                float e0, e1;
                EX2F(e0, acc[mt][nt][half * 2 + 0] * SCALE_L2E + mcol[nt][0]);
                EX2F(e1, acc[mt][nt][half * 2 + 1] * SCALE_L2E + mcol[nt][1]);
                rs += e0 + e1;
                *(__half2*)&sE[lrow * EPAD + lcol] = __floats2half2_rn(e0, e1);
            }
            rs += __shfl_xor_sync(0xffffffffu, rs, 1);
            rs += __shfl_xor_sync(0xffffffffu, rs, 2);
            if ((lane & 3) == 0)
                rowsum[((size_t)z * SS + blockRow + lrow) * RS_W + blockIdx.x * 4 + (wid & 3)] = rs;
        }
    }
    __syncthreads();

    __half* Ez = eout + (size_t)z * SS * SS;
#pragma unroll
    for (int i = 0; i < 8; i++) {
        int id = tid + i * 256;
        int row = id >> 4, q = id & 15;
        uint4 v = *(const uint4*)&sE[row * EPAD + q * 8];
        STG_CS_U4(&Ez[(size_t)(blockRow + row) * SS + blockCol + q * 8], v);
    }
}

// ==================== AV: cp.async pipelined, .cs attn stores ================
#define AVPAD 72
#define AV_STAGE   46080      // A 256*72*2 + B 64*72*2
#define AV_OFF_B   36864
#define AV_OFF_INV 92160      // after 2 stages
#define AV_SMEM    93184      // + 256*4

__global__ __launch_bounds__(256, 2)
void av_mma_kernel(const __half* __restrict__ e, const __half* __restrict__ vt,
                   const float* __restrict__ rowsum, float* __restrict__ attn,
                   __half* __restrict__ of)
{
    extern __shared__ char avsm[];
    const uint32_t sb0 = smem_u32(avsm);
    float* invs = (float*)(avsm + AV_OFF_INV);

    const int z = blockIdx.y;
    const int b = z / NUM_HEADS, h = z % NUM_HEADS;
    const int rowbase = blockIdx.x * 256;
    const int tid = threadIdx.x, lane = tid & 31, wid = tid >> 5;
    const int warpM = wid * 32;
    const int lmRow = lane & 15, lmK = (lane >> 4) * 8;

    {
        const float4* rp = (const float4*)&rowsum[((size_t)z * SS + rowbase + tid) * RS_W];
        float s = 0.0f;
#pragma unroll
        for (int j = 0; j < RS_W / 4; j++) {
            float4 v = rp[j];
            s += (v.x + v.y) + (v.z + v.w);
        }
        invs[tid] = 1.0f / s;
    }
    __syncthreads();

    const __half* Ez = e + (size_t)z * SS * SS;
    float* Az = attn + (size_t)z * SS * SS;

    auto load_stage = [&](int stage, int chunk) {
        const int k0 = chunk * 64;
        const uint32_t sb = sb0 + stage * AV_STAGE;
#pragma unroll
        for (int i = 0; i < 8; i++) {
            int id = tid + i * 256;
            int row = id >> 3, q = id & 7;
            CP16(sb + (uint32_t)(row * 144 + q * 16),
                 &Ez[(size_t)(rowbase + row) * SS + k0 + q * 8]);
        }
#pragma unroll
        for (int i = 0; i < 2; i++) {
            int id = tid + i * 256;
            int row = id >> 3, q = id & 7;
            CP16(sb + AV_OFF_B + (uint32_t)(row * 144 + q * 16),
                 &vt[((size_t)z * DEPTH + row) * SS + k0 + q * 8]);
        }
        CP_COMMIT();
    };

    float acc[2][8][4];
#pragma unroll
    for (int mt = 0; mt < 2; mt++)
#pragma unroll
        for (int nt = 0; nt < 8; nt++)
#pragma unroll
            for (int r = 0; r < 4; r++) acc[mt][nt][r] = 0.0f;

    load_stage(0, 0);

    for (int chunk = 0; chunk < 32; chunk++) {
        if (chunk < 31) { load_stage((chunk + 1) & 1, chunk + 1); CP_WAIT1(); }
        else           { CP_WAIT0(); }
        __syncthreads();

        const uint32_t sb = sb0 + (chunk & 1) * AV_STAGE;
        const __half* sA = (const __half*)(avsm + (chunk & 1) * AV_STAGE);
        const uint32_t aBase = sb + (uint32_t)(((warpM + lmRow) * AVPAD + lmK) * 2);
        const uint32_t bBase = sb + AV_OFF_B + (uint32_t)((lmRow * AVPAD + lmK) * 2);

        // MMA first (tensor pipe starts immediately)
#pragma unroll
        for (int ks = 0; ks < 4; ks++) {
            const uint32_t kOff = (uint32_t)(ks * 16 * 2);
            uint32_t aF[2][4], bH[8][2];
#pragma unroll
            for (int mt = 0; mt < 2; mt++) {
                uint32_t ad = aBase + kOff + (uint32_t)(mt * 16 * AVPAD * 2);
                LDSM4(aF[mt][0], aF[mt][1], aF[mt][2], aF[mt][3], ad);
            }
#pragma unroll
            for (int ntp = 0; ntp < 4; ntp++) {
                uint32_t bd = bBase + kOff + (uint32_t)(ntp * 16 * AVPAD * 2);
                uint32_t r0, r1, r2, r3;
                LDSM4(r0, r1, r2, r3, bd);
                bH[2 * ntp][0] = r0; bH[2 * ntp + 1][0] = r1;
                bH[2 * ntp][1] = r2; bH[2 * ntp + 1][1] = r3;
            }
#pragma unroll
            for (int mt = 0; mt < 2; mt++)
#pragma unroll
                for (int nt = 0; nt < 8; nt++)
                    MMAH(acc[mt][nt], aF[mt], bH[nt]);
        }

        // normalize + attn write (streaming .cs stores)
        const int k0 = chunk * 64;
#pragma unroll
        for (int i = 0; i < 8; i++) {
            int id = tid + i * 256;
            int row = id >> 3, q = id & 7;
            uint4 ev = *(const uint4*)&sA[row * AVPAD + q * 8];
            const float inv = invs[row];
            const __half2* hp = (const __half2*)&ev;
            float2 f0 = __half22float2(hp[0]);
            float2 f1 = __half22float2(hp[1]);
            float2 f2 = __half22float2(hp[2]);
            float2 f3 = __half22float2(hp[3]);
            float4 v0 = {f0.x * inv, f0.y * inv, f1.x * inv, f1.y * inv};
            float4 v1 = {f2.x * inv, f2.y * inv, f3.x * inv, f3.y * inv};
            size_t ao = (size_t)(rowbase + row) * SS + k0 + q * 8;
            STG_CS_F4(&Az[ao],     v0);
            STG_CS_F4(&Az[ao + 4], v1);
        }
        __syncthreads();
    }

#pragma unroll
    for (int mt = 0; mt < 2; mt++) {
#pragma unroll
        for (int nt = 0; nt < 8; nt++) {
            int lrow0 = warpM + mt * 16 + (lane >> 2);
            int col   = nt * 8 + (lane & 3) * 2;
#pragma unroll
            for (int half = 0; half < 2; half++) {
                int lr = lrow0 + half * 8;
                float inv = invs[lr];
                int r = rowbase + lr;
                float vx = acc[mt][nt][half * 2 + 0] * inv;
                float vy = acc[mt][nt][half * 2 + 1] * inv;
                size_t o = ((size_t)b * SS + r) * D_MODEL + h * DEPTH + col;
                __half2 hp = {__float2half(vx), __float2half(vy)};
                *(__half2*)&of[o] = hp;
            }
        }
    }
}

// =====================================================================
extern "C" void kernel_launch(void* const* d_in, const int* in_sizes, int n_in,
                              void* d_out, int out_size)
{
    const float* Q    = (const float*)d_in[0];
    const float* K    = (const float*)d_in[1];
    const float* V    = (const float*)d_in[2];
    const float* mask = (const float*)d_in[3];
    const float* Wq   = (const float*)d_in[4];
    const float* bq   = (const float*)d_in[5];
    const float* Wk   = (const float*)d_in[6];
    const float* bk   = (const float*)d_in[7];
    const float* Wv   = (const float*)d_in[8];
    const float* bv   = (const float*)d_in[9];
    const float* Wo   = (const float*)d_in[10];
    const float* bo   = (const float*)d_in[11];

    float* out = (float*)d_out;

    float *rowsum, *attn;
    __half *inb, *w, *qf, *kf, *vt, *of, *ebuf;
    cudaGetSymbolAddress((void**)&rowsum, g_rowsum);
    cudaGetSymbolAddress((void**)&ebuf, g_e);
    cudaGetSymbolAddress((void**)&inb, g_in);
    cudaGetSymbolAddress((void**)&w, g_w);
    cudaGetSymbolAddress((void**)&qf, g_q_f);
    cudaGetSymbolAddress((void**)&kf, g_k_f);
    cudaGetSymbolAddress((void**)&vt, g_vt);
    cudaGetSymbolAddress((void**)&of, g_o_f);

    if ((size_t)out_size >= OUT_ELEMS + ATTN_ELEMS) {
        attn = out + OUT_ELEMS;
    } else {
        cudaGetSymbolAddress((void**)&attn, g_attn_fallback);
    }

    static bool attr_done = false;
    if (!attr_done) {
        cudaFuncSetAttribute(proj_qkv_kernel, cudaFuncAttributeMaxDynamicSharedMemorySize, 2 * P2STAGE);
        cudaFuncSetAttribute(proj_out_kernel, cudaFuncAttributeMaxDynamicSharedMemorySize, 2 * P2STAGE);
        cudaFuncSetAttribute(scores_mma_kernel, cudaFuncAttributeMaxDynamicSharedMemorySize, 2 * 128 * QPAD * 2);
        cudaFuncSetAttribute(av_mma_kernel, cudaFuncAttributeMaxDynamicSharedMemorySize, AV_SMEM);
        attr_done = true;
    }

    // 1. splits
    dim3 wtBlock(32, 8);
    split_w4_kernel<<<dim3(32, 32, 4), wtBlock>>>(Wq, Wk, Wv, Wo, w);
    split_in3_kernel<<<dim3(NELEM / 1024, 3), 256>>>(Q, K, V, inb);

    // 2. QKV projections
    proj_qkv_kernel<<<dim3(8, 32, 3), 256, 2 * P2STAGE>>>(
        inb, w, bq, bk, bv, qf, kf, vt);

    // 3. scores -> e fp16 (.cs) + rowsum partials
    scores_mma_kernel<<<dim3(16, 16, NZ), 256, 2 * 128 * QPAD * 2>>>(
        qf, kf, mask, ebuf, rowsum);

    // 4. AV (cp.async pipelined) + fused attn normalize (.cs stores)
    av_mma_kernel<<<dim3(8, NZ), 256, AV_SMEM>>>(ebuf, vt, rowsum, attn, of);

    // 5. output projection
    proj_out_kernel<<<dim3(8, 32), 256, 2 * P2STAGE>>>(
        of, w + (size_t)3 * WELEM, bo, out);
}